// round 11
// baseline (speedup 1.0000x reference)
#include <cuda_runtime.h>
#include <cuda_bf16.h>
#include <math.h>
#include <stdint.h>

#define T_TOKENS 1024
#define H_DIM    2048
#define I_DIM    1408
#define SI_DIM   5632
#define NE       8

typedef __nv_bfloat16 bf16;
typedef __nv_bfloat162 bf162;

// ---------------------------------------------------------------------------
// Scratch (__device__ globals; no cudaMalloc allowed)
// ---------------------------------------------------------------------------
__device__ int   g_cnt[NE];
__device__ int   g_tok [NE * T_TOKENS];
__device__ int   g_slot[NE * T_TOKENS];
__device__ float g_wt  [NE * T_TOKENS];
__device__ float g_sgate[T_TOKENS];

__device__ bf16 g_hid_hi[(size_t)T_TOKENS * H_DIM];
__device__ bf16 g_hid_lo[(size_t)T_TOKENS * H_DIM];

__device__ bf16  g_act_hi[(size_t)NE * T_TOKENS * I_DIM];
__device__ bf16  g_act_lo[(size_t)NE * T_TOKENS * I_DIM];
__device__ bf16  g_shact_hi[(size_t)T_TOKENS * SI_DIM];
__device__ bf16  g_shact_lo[(size_t)T_TOKENS * SI_DIM];
__device__ float g_contrib[(size_t)T_TOKENS * 2 * H_DIM];

// ---------------------------------------------------------------------------
__global__ void zero_cnt_kernel() {
    if (threadIdx.x < NE) g_cnt[threadIdx.x] = 0;
}

__global__ __launch_bounds__(256) void router_kernel(
    const float* __restrict__ hidden,
    const float* __restrict__ gate_w,
    const float* __restrict__ shared_gate_w,
    float* __restrict__ out_logits)
{
    const int t = blockIdx.x;
    __shared__ float sh[H_DIM];
    __shared__ float slog[NE];
    __shared__ float sred[256];

    const float* hrow = hidden + (size_t)t * H_DIM;
    for (int i = threadIdx.x; i < H_DIM; i += 256) sh[i] = hrow[i];
    __syncthreads();

    const int warp = threadIdx.x >> 5;
    const int lane = threadIdx.x & 31;

    float sum = 0.f;
    for (int k = lane; k < H_DIM; k += 32) sum += sh[k] * gate_w[k * NE + warp];
    #pragma unroll
    for (int o = 16; o; o >>= 1) sum += __shfl_down_sync(0xffffffffu, sum, o);
    if (lane == 0) slog[warp] = sum;

    float s2 = 0.f;
    for (int k = threadIdx.x; k < H_DIM; k += 256) s2 += sh[k] * shared_gate_w[k];
    sred[threadIdx.x] = s2;
    __syncthreads();
    for (int st = 128; st; st >>= 1) {
        if (threadIdx.x < st) sred[threadIdx.x] += sred[threadIdx.x + st];
        __syncthreads();
    }

    if (threadIdx.x == 0) {
        float lg[NE];
        float mx = -1e30f;
        #pragma unroll
        for (int e = 0; e < NE; ++e) { lg[e] = slog[e]; mx = fmaxf(mx, lg[e]); }
        float p[NE]; float den = 0.f;
        #pragma unroll
        for (int e = 0; e < NE; ++e) { p[e] = expf(lg[e] - mx); den += p[e]; }
        float inv = 1.f / den;
        #pragma unroll
        for (int e = 0; e < NE; ++e) {
            p[e] *= inv;
            out_logits[(size_t)t * NE + e] = lg[e];
        }
        int i0 = 0;
        #pragma unroll
        for (int e = 1; e < NE; ++e) if (p[e] > p[i0]) i0 = e;
        int i1 = -1;
        #pragma unroll
        for (int e = 0; e < NE; ++e) {
            if (e == i0) continue;
            if (i1 < 0 || p[e] > p[i1]) i1 = e;
        }
        int pos0 = atomicAdd(&g_cnt[i0], 1);
        g_tok [i0 * T_TOKENS + pos0] = t;
        g_slot[i0 * T_TOKENS + pos0] = 0;
        g_wt  [i0 * T_TOKENS + pos0] = p[i0];
        int pos1 = atomicAdd(&g_cnt[i1], 1);
        g_tok [i1 * T_TOKENS + pos1] = t;
        g_slot[i1 * T_TOKENS + pos1] = 1;
        g_wt  [i1 * T_TOKENS + pos1] = p[i1];

        g_sgate[t] = 1.f / (1.f + expf(-sred[0]));
    }
}

// ---------------------------------------------------------------------------
// fp32 -> bf16 hi/lo split (hidden only: 8MB, ~4us)
// ---------------------------------------------------------------------------
__global__ __launch_bounds__(256) void split_kernel(
    const float* __restrict__ src, bf16* __restrict__ hi, bf16* __restrict__ lo, int n4)
{
    for (int i = blockIdx.x * 256 + threadIdx.x; i < n4; i += gridDim.x * 256) {
        float4 v = ((const float4*)src)[i];
        bf16 hx = __float2bfloat16_rn(v.x);
        bf16 hy = __float2bfloat16_rn(v.y);
        bf16 hz = __float2bfloat16_rn(v.z);
        bf16 hw = __float2bfloat16_rn(v.w);
        bf16 lx = __float2bfloat16_rn(v.x - __bfloat162float(hx));
        bf16 ly = __float2bfloat16_rn(v.y - __bfloat162float(hy));
        bf16 lz = __float2bfloat16_rn(v.z - __bfloat162float(hz));
        bf16 lw = __float2bfloat16_rn(v.w - __bfloat162float(hw));
        ((bf162*)hi)[2 * i]     = bf162(hx, hy);
        ((bf162*)hi)[2 * i + 1] = bf162(hz, hw);
        ((bf162*)lo)[2 * i]     = bf162(lx, ly);
        ((bf162*)lo)[2 * i + 1] = bf162(lz, lw);
    }
}

// ---------------------------------------------------------------------------
// helpers
// ---------------------------------------------------------------------------
__device__ __forceinline__ uint32_t smem_u32(const void* p) {
    return (uint32_t)__cvta_generic_to_shared(p);
}
__device__ __forceinline__ void ldsm_x4(uint32_t* r, uint32_t a) {
    asm volatile("ldmatrix.sync.aligned.m8n8.x4.shared.b16 {%0,%1,%2,%3}, [%4];"
                 : "=r"(r[0]), "=r"(r[1]), "=r"(r[2]), "=r"(r[3]) : "r"(a));
}
__device__ __forceinline__ void ldsm_x4_t(uint32_t* r, uint32_t a) {
    asm volatile("ldmatrix.sync.aligned.m8n8.x4.trans.shared.b16 {%0,%1,%2,%3}, [%4];"
                 : "=r"(r[0]), "=r"(r[1]), "=r"(r[2]), "=r"(r[3]) : "r"(a));
}
__device__ __forceinline__ void mma16816(float* d, const uint32_t* a, uint32_t b0, uint32_t b1) {
    asm volatile("mma.sync.aligned.m16n8k16.row.col.f32.bf16.bf16.f32 "
                 "{%0,%1,%2,%3}, {%4,%5,%6,%7}, {%8,%9}, {%0,%1,%2,%3};"
                 : "+f"(d[0]), "+f"(d[1]), "+f"(d[2]), "+f"(d[3])
                 : "r"(a[0]), "r"(a[1]), "r"(a[2]), "r"(a[3]), "r"(b0), "r"(b1));
}
__device__ __forceinline__ void split4(const float4& v, uint2& hi, uint2& lo) {
    bf16 h0 = __float2bfloat16_rn(v.x), h1 = __float2bfloat16_rn(v.y);
    bf16 h2 = __float2bfloat16_rn(v.z), h3 = __float2bfloat16_rn(v.w);
    bf162 H0(h0, h1), H1(h2, h3);
    bf162 L0(__float2bfloat16_rn(v.x - __bfloat162float(h0)),
             __float2bfloat16_rn(v.y - __bfloat162float(h1)));
    bf162 L1(__float2bfloat16_rn(v.z - __bfloat162float(h2)),
             __float2bfloat16_rn(v.w - __bfloat162float(h3)));
    hi.x = *reinterpret_cast<uint32_t*>(&H0); hi.y = *reinterpret_cast<uint32_t*>(&H1);
    lo.x = *reinterpret_cast<uint32_t*>(&L0); lo.y = *reinterpret_cast<uint32_t*>(&L1);
}
__device__ __forceinline__ void split2(float a, float b, uint32_t& hi, uint32_t& lo) {
    bf16 h0 = __float2bfloat16_rn(a), h1 = __float2bfloat16_rn(b);
    bf162 H(h0, h1);
    bf162 L(__float2bfloat16_rn(a - __bfloat162float(h0)),
            __float2bfloat16_rn(b - __bfloat162float(h1)));
    hi = *reinterpret_cast<uint32_t*>(&H);
    lo = *reinterpret_cast<uint32_t*>(&L);
}

#define CP16(dst, src) \
    asm volatile("cp.async.cg.shared.global [%0], [%1], 16;" :: "r"(dst), "l"(src) : "memory")
#define CP_COMMIT() asm volatile("cp.async.commit_group;" ::: "memory")
#define CP_WAIT(n)  asm volatile("cp.async.wait_group %0;" :: "n"(n) : "memory")

// ---------------------------------------------------------------------------
// bf16 hi/lo 3-term GEMM. A bf16 hi/lo via cp.async (double buffer).
// B fp32 from gmem, register-staged split -> smem bf16 hi/lo.
// CTA tile M=128 x TILE_N, 256 threads = 8 warps (4m x 2n), warp tile 32 x TILE_N/2.
// DUAL=1: TILE_N = [gate(TILE_N/2)|up(TILE_N/2)] at col n0 of each matrix;
//         grid.x step TILE_N/2. Non-dual: grid.x step TILE_N.
// EPI: 0 = silu(gate)*up -> bf16 hi/lo; 1 = expert scatter x weight;
//      2 = shared combine (sigmoid gate + contrib -> outF).
// ---------------------------------------------------------------------------
#define ASTRIDE 80
#define ALO_OFF 10240

template<int GATHER, int AEXP, int DUAL, int EPI, int TILE_N>
__global__ void __launch_bounds__(256, 2) mma2_gemm(
    const bf16* __restrict__ Ahi, const bf16* __restrict__ Alo,
    const float* __restrict__ B0, const float* __restrict__ B1,
    bf16* __restrict__ outHi, bf16* __restrict__ outLo,
    float* __restrict__ outF, int K, int Ntot)
{
    constexpr int NW   = TILE_N / 2;       // cols per n-warp
    constexpr int NJ   = NW / 8;           // acc col groups
    constexpr int CPT  = TILE_N / 8;       // B cols per loader thread
    constexpr int NF4  = CPT / 4;          // float4 per loader thread
    constexpr int BSTR = TILE_N * 2 + 16;  // B smem row stride (bytes)
    constexpr int BSZ  = 32 * BSTR;
    constexpr int BHI  = 20480;
    constexpr int BLOO = 20480 + BSZ;
    constexpr int STG  = 20480 + 2 * BSZ;

    const int e  = blockIdx.z;
    const int m0 = blockIdx.y * 128;
    const int n0 = blockIdx.x * (DUAL ? NW : TILE_N);
    const int cnt = (GATHER || AEXP) ? g_cnt[e] : T_TOKENS;
    if (m0 >= cnt) return;

    extern __shared__ char db[];
    __shared__ int s_tok[128];

    const int tid  = threadIdx.x;
    const int lane = tid & 31;
    const int warp = tid >> 5;
    const int wm = warp & 3;
    const int wn = warp >> 2;

    if (GATHER && tid < 128) {
        int gm = m0 + tid;
        s_tok[tid] = (gm < cnt) ? g_tok[e * T_TOKENS + gm] : 0;
    }
    __syncthreads();

    // ---- A loader (cp.async): thread -> row tid>>1, 16 k elems at (tid&1)*16 ----
    const int arow_l = tid >> 1;
    size_t arow;
    if (GATHER) arow = (size_t)s_tok[arow_l];
    else        arow = (AEXP ? (size_t)e * T_TOKENS : 0) + m0 + arow_l;
    const bf16* aHiP = Ahi + arow * K + (tid & 1) * 16;
    const bf16* aLoP = Alo + arow * K + (tid & 1) * 16;
    const uint32_t aDst = smem_u32(db) + (uint32_t)(arow_l * ASTRIDE + (tid & 1) * 32);

    auto issueA = [&](int k0, int s) {
        const uint32_t so = (uint32_t)(s * STG);
        CP16(aDst + so,      aHiP + k0);
        CP16(aDst + so + 16, aHiP + k0 + 8);
        CP16(aDst + so + ALO_OFF,      aLoP + k0);
        CP16(aDst + so + ALO_OFF + 16, aLoP + k0 + 8);
    };

    // ---- B loader (fp32 LDG + split): k-row tid>>3, CPT cols at (tid&7)*CPT ----
    const int bkr = tid >> 3;
    const int seg = (tid & 7) * CPT;
    const size_t eoff = (GATHER || AEXP) ? (size_t)e * K * Ntot : 0;
    const float* BP;
    if (DUAL) BP = (seg < NW ? B0 + eoff + n0 + seg : B1 + eoff + n0 + seg - NW);
    else      BP = B0 + eoff + n0 + seg;
    BP += (size_t)bkr * Ntot;
    const uint32_t bOff = (uint32_t)(bkr * BSTR + seg * 2);

    float4 pb[NF4];
    auto ldgB = [&](int k0) {
        const float4* p = (const float4*)(BP + (size_t)k0 * Ntot);
        #pragma unroll
        for (int i = 0; i < NF4; ++i) pb[i] = p[i];
    };
    auto stsB = [&](int s) {
        char* st = db + s * STG;
        #pragma unroll
        for (int i = 0; i < NF4 / 2; ++i) {
            uint2 h0, l0, h1, l1;
            split4(pb[2 * i], h0, l0); split4(pb[2 * i + 1], h1, l1);
            *(uint4*)(st + BHI  + bOff + i * 16) = make_uint4(h0.x, h0.y, h1.x, h1.y);
            *(uint4*)(st + BLOO + bOff + i * 16) = make_uint4(l0.x, l0.y, l1.x, l1.y);
        }
    };

    float acc[2][NJ][4];
    #pragma unroll
    for (int i = 0; i < 2; ++i)
        #pragma unroll
        for (int j = 0; j < NJ; ++j)
            #pragma unroll
            for (int v = 0; v < 4; ++v) acc[i][j][v] = 0.f;

    const int grp = lane >> 3;
    const int gl  = lane & 7;
    const int a_row_off = (grp & 1) * 8 + gl;
    const int a_col_off = (grp >> 1) * 8;
    const int b_row_off = (grp & 1) * 8 + gl;
    const int b_col_off = (grp >> 1) * 8;

    const int C = K / 32;
    ldgB(0);
    issueA(0, 0);
    CP_COMMIT();

    for (int c = 0; c < C; ++c) {
        if (c + 1 < C) {
            issueA((c + 1) * 32, (c + 1) & 1);
            CP_COMMIT();
            CP_WAIT(1);
        } else {
            CP_WAIT(0);
        }
        stsB(c & 1);
        if (c + 1 < C) ldgB((c + 1) * 32);
        __syncthreads();

        const uint32_t base = smem_u32(db) + (uint32_t)((c & 1) * STG);
        #pragma unroll
        for (int ks = 0; ks < 32; ks += 16) {
            uint32_t ah[2][4], al[2][4];
            #pragma unroll
            for (int mi = 0; mi < 2; ++mi) {
                const uint32_t ra = base + (uint32_t)((wm * 32 + mi * 16 + a_row_off) * ASTRIDE + (ks + a_col_off) * 2);
                ldsm_x4(ah[mi], ra);
                ldsm_x4(al[mi], ra + ALO_OFF);
            }
            #pragma unroll
            for (int g = 0; g < NW / 16; ++g) {
                uint32_t bh[4], bl[4];
                const uint32_t rb = base + (uint32_t)(BHI + (ks + b_row_off) * BSTR + (wn * NW + g * 16 + b_col_off) * 2);
                ldsm_x4_t(bh, rb);
                ldsm_x4_t(bl, rb + BSZ);
                #pragma unroll
                for (int mi = 0; mi < 2; ++mi) {
                    #pragma unroll
                    for (int half = 0; half < 2; ++half) {
                        const int nj = g * 2 + half;
                        const int p = half * 2;
                        mma16816(acc[mi][nj], ah[mi], bh[p], bh[p + 1]);
                        mma16816(acc[mi][nj], ah[mi], bl[p], bl[p + 1]);
                        mma16816(acc[mi][nj], al[mi], bh[p], bh[p + 1]);
                    }
                }
            }
        }
        __syncthreads();
    }

    // ---- epilogues ----
    if (EPI == 0) {
        constexpr int EXS = NW + 8;
        float* exch = (float*)db;   // [128][EXS]
        if (wn == 1) {
            #pragma unroll
            for (int mi = 0; mi < 2; ++mi)
                #pragma unroll
                for (int nj = 0; nj < NJ; ++nj) {
                    const int cl = nj * 8 + (lane & 3) * 2;
                    #pragma unroll
                    for (int h = 0; h < 2; ++h) {
                        const int rl = wm * 32 + mi * 16 + (lane >> 2) + h * 8;
                        exch[rl * EXS + cl]     = acc[mi][nj][h * 2];
                        exch[rl * EXS + cl + 1] = acc[mi][nj][h * 2 + 1];
                    }
                }
        }
        __syncthreads();
        if (wn == 0) {
            #pragma unroll
            for (int mi = 0; mi < 2; ++mi)
                #pragma unroll
                for (int h = 0; h < 2; ++h) {
                    const int rl = wm * 32 + mi * 16 + (lane >> 2) + h * 8;
                    const int r = m0 + rl;
                    if (GATHER && r >= cnt) continue;
                    const size_t row = (GATHER ? (size_t)e * T_TOKENS : 0) + r;
                    #pragma unroll
                    for (int nj = 0; nj < NJ; ++nj) {
                        const int cl = nj * 8 + (lane & 3) * 2;
                        const float g0 = acc[mi][nj][h * 2];
                        const float g1 = acc[mi][nj][h * 2 + 1];
                        const float u0 = exch[rl * EXS + cl];
                        const float u1 = exch[rl * EXS + cl + 1];
                        const float a0 = (g0 / (1.f + expf(-g0))) * u0;
                        const float a1 = (g1 / (1.f + expf(-g1))) * u1;
                        uint32_t hi, lo; split2(a0, a1, hi, lo);
                        *(uint32_t*)(outHi + row * Ntot + n0 + cl) = hi;
                        *(uint32_t*)(outLo + row * Ntot + n0 + cl) = lo;
                    }
                }
        }
    } else {
        #pragma unroll
        for (int mi = 0; mi < 2; ++mi)
            #pragma unroll
            for (int h = 0; h < 2; ++h) {
                const int rl = wm * 32 + mi * 16 + (lane >> 2) + h * 8;
                const int r = m0 + rl;
                if (EPI == 1) {
                    if (r >= cnt) continue;
                    const int idx = e * T_TOKENS + r;
                    const float w = g_wt[idx];
                    float* orow = g_contrib + ((size_t)g_tok[idx] * 2 + g_slot[idx]) * H_DIM;
                    #pragma unroll
                    for (int nj = 0; nj < NJ; ++nj) {
                        const int c = n0 + wn * NW + nj * 8 + (lane & 3) * 2;
                        float2 o = {acc[mi][nj][h * 2] * w, acc[mi][nj][h * 2 + 1] * w};
                        *(float2*)(orow + c) = o;
                    }
                } else {
                    const float sg = g_sgate[r];
                    #pragma unroll
                    for (int nj = 0; nj < NJ; ++nj) {
                        const int c = n0 + wn * NW + nj * 8 + (lane & 3) * 2;
                        const float2 c0 = *(const float2*)(g_contrib + ((size_t)r * 2 + 0) * H_DIM + c);
                        const float2 c1 = *(const float2*)(g_contrib + ((size_t)r * 2 + 1) * H_DIM + c);
                        float2 o = {sg * acc[mi][nj][h * 2] + c0.x + c1.x,
                                    sg * acc[mi][nj][h * 2 + 1] + c0.y + c1.y};
                        *(float2*)(outF + (size_t)r * H_DIM + c) = o;
                    }
                }
            }
    }
}

// ---------------------------------------------------------------------------
extern "C" void kernel_launch(void* const* d_in, const int* in_sizes, int n_in,
                              void* d_out, int out_size)
{
    const float* hidden        = (const float*)d_in[0];
    const float* gate_w        = (const float*)d_in[1];
    const float* w_gate        = (const float*)d_in[2];
    const float* w_up          = (const float*)d_in[3];
    const float* w_down        = (const float*)d_in[4];
    const float* sw_gate       = (const float*)d_in[5];
    const float* sw_up         = (const float*)d_in[6];
    const float* sw_down       = (const float*)d_in[7];
    const float* shared_gate_w = (const float*)d_in[8];

    float* out        = (float*)d_out;
    float* out_logits = out + (size_t)T_TOKENS * H_DIM;

    bf16 *hidHi, *hidLo, *actHi, *actLo, *shHi, *shLo;
    cudaGetSymbolAddress((void**)&hidHi, g_hid_hi);  cudaGetSymbolAddress((void**)&hidLo, g_hid_lo);
    cudaGetSymbolAddress((void**)&actHi, g_act_hi);  cudaGetSymbolAddress((void**)&actLo, g_act_lo);
    cudaGetSymbolAddress((void**)&shHi, g_shact_hi); cudaGetSymbolAddress((void**)&shLo, g_shact_lo);

    // stage sizes: TILE_N=128 -> 37888*2 = 75776 ; TILE_N=64 -> 29696*2 = 59392
    const int SM128 = 2 * (20480 + 2 * (32 * (128 * 2 + 16)));
    const int SM64  = 2 * (20480 + 2 * (32 * (64 * 2 + 16)));

    cudaFuncSetAttribute(mma2_gemm<1,0,1,0,64>,  cudaFuncAttributeMaxDynamicSharedMemorySize, SM64);
    cudaFuncSetAttribute(mma2_gemm<0,1,0,1,128>, cudaFuncAttributeMaxDynamicSharedMemorySize, SM128);
    cudaFuncSetAttribute(mma2_gemm<0,0,1,0,128>, cudaFuncAttributeMaxDynamicSharedMemorySize, SM128);
    cudaFuncSetAttribute(mma2_gemm<0,0,0,2,64>,  cudaFuncAttributeMaxDynamicSharedMemorySize, SM64);

    zero_cnt_kernel<<<1, 32>>>();
    router_kernel<<<T_TOKENS, 256>>>(hidden, gate_w, shared_gate_w, out_logits);

    // hidden split only (8MB, ~4us)
    {
        int n4 = (int)((size_t)T_TOKENS * H_DIM / 4);
        split_kernel<<<(n4 + 255) / 256, 256>>>(hidden, hidHi, hidLo, n4);
    }

    // expert gate+up -> act hi/lo  (32 cols per matrix per CTA -> better wave balance)
    mma2_gemm<1,0,1,0,64><<<dim3(I_DIM / 32, T_TOKENS / 128, NE), 256, SM64>>>(
        hidHi, hidLo, w_gate, w_up, actHi, actLo, nullptr, H_DIM, I_DIM);
    // expert down -> contrib scatter (128-wide, already single-wave)
    mma2_gemm<0,1,0,1,128><<<dim3(H_DIM / 128, T_TOKENS / 128, NE), 256, SM128>>>(
        actHi, actLo, w_down, w_down, nullptr, nullptr, nullptr, I_DIM, H_DIM);
    // shared gate+up -> shact hi/lo (64 cols per matrix per CTA)
    mma2_gemm<0,0,1,0,128><<<dim3(SI_DIM / 64, T_TOKENS / 128, 1), 256, SM128>>>(
        hidHi, hidLo, sw_gate, sw_up, shHi, shLo, nullptr, H_DIM, SI_DIM);
    // shared down + combine -> out (64-wide tiles -> 256 CTAs, full wave)
    mma2_gemm<0,0,0,2,64><<<dim3(H_DIM / 64, T_TOKENS / 128, 1), 256, SM64>>>(
        shHi, shLo, sw_down, sw_down, nullptr, nullptr, out, SI_DIM, H_DIM);
}

// round 12
// speedup vs baseline: 1.0682x; 1.0682x over previous
#include <cuda_runtime.h>
#include <cuda_bf16.h>
#include <math.h>
#include <stdint.h>

#define T_TOKENS 1024
#define H_DIM    2048
#define I_DIM    1408
#define SI_DIM   5632
#define NE       8

typedef __nv_bfloat16 bf16;
typedef __nv_bfloat162 bf162;

// ---------------------------------------------------------------------------
// Scratch (__device__ globals; no cudaMalloc allowed)
// ---------------------------------------------------------------------------
__device__ int   g_cnt[NE];
__device__ int   g_tok [NE * T_TOKENS];
__device__ int   g_slot[NE * T_TOKENS];
__device__ float g_wt  [NE * T_TOKENS];
__device__ float g_sgate[T_TOKENS];

__device__ bf16 g_hid_hi[(size_t)T_TOKENS * H_DIM];
__device__ bf16 g_hid_lo[(size_t)T_TOKENS * H_DIM];

__device__ bf16  g_act_hi[(size_t)NE * T_TOKENS * I_DIM];
__device__ bf16  g_act_lo[(size_t)NE * T_TOKENS * I_DIM];
__device__ bf16  g_shact_hi[(size_t)T_TOKENS * SI_DIM];
__device__ bf16  g_shact_lo[(size_t)T_TOKENS * SI_DIM];
__device__ float g_contrib[(size_t)T_TOKENS * 2 * H_DIM];

// ---------------------------------------------------------------------------
__global__ void zero_cnt_kernel() {
    if (threadIdx.x < NE) g_cnt[threadIdx.x] = 0;
}

__global__ __launch_bounds__(256) void router_kernel(
    const float* __restrict__ hidden,
    const float* __restrict__ gate_w,
    const float* __restrict__ shared_gate_w,
    float* __restrict__ out_logits)
{
    const int t = blockIdx.x;
    __shared__ float sh[H_DIM];
    __shared__ float slog[NE];
    __shared__ float sred[256];

    const float* hrow = hidden + (size_t)t * H_DIM;
    for (int i = threadIdx.x; i < H_DIM; i += 256) sh[i] = hrow[i];
    __syncthreads();

    const int warp = threadIdx.x >> 5;
    const int lane = threadIdx.x & 31;

    float sum = 0.f;
    for (int k = lane; k < H_DIM; k += 32) sum += sh[k] * gate_w[k * NE + warp];
    #pragma unroll
    for (int o = 16; o; o >>= 1) sum += __shfl_down_sync(0xffffffffu, sum, o);
    if (lane == 0) slog[warp] = sum;

    float s2 = 0.f;
    for (int k = threadIdx.x; k < H_DIM; k += 256) s2 += sh[k] * shared_gate_w[k];
    sred[threadIdx.x] = s2;
    __syncthreads();
    for (int st = 128; st; st >>= 1) {
        if (threadIdx.x < st) sred[threadIdx.x] += sred[threadIdx.x + st];
        __syncthreads();
    }

    if (threadIdx.x == 0) {
        float lg[NE];
        float mx = -1e30f;
        #pragma unroll
        for (int e = 0; e < NE; ++e) { lg[e] = slog[e]; mx = fmaxf(mx, lg[e]); }
        float p[NE]; float den = 0.f;
        #pragma unroll
        for (int e = 0; e < NE; ++e) { p[e] = expf(lg[e] - mx); den += p[e]; }
        float inv = 1.f / den;
        #pragma unroll
        for (int e = 0; e < NE; ++e) {
            p[e] *= inv;
            out_logits[(size_t)t * NE + e] = lg[e];
        }
        int i0 = 0;
        #pragma unroll
        for (int e = 1; e < NE; ++e) if (p[e] > p[i0]) i0 = e;
        int i1 = -1;
        #pragma unroll
        for (int e = 0; e < NE; ++e) {
            if (e == i0) continue;
            if (i1 < 0 || p[e] > p[i1]) i1 = e;
        }
        int pos0 = atomicAdd(&g_cnt[i0], 1);
        g_tok [i0 * T_TOKENS + pos0] = t;
        g_slot[i0 * T_TOKENS + pos0] = 0;
        g_wt  [i0 * T_TOKENS + pos0] = p[i0];
        int pos1 = atomicAdd(&g_cnt[i1], 1);
        g_tok [i1 * T_TOKENS + pos1] = t;
        g_slot[i1 * T_TOKENS + pos1] = 1;
        g_wt  [i1 * T_TOKENS + pos1] = p[i1];

        g_sgate[t] = 1.f / (1.f + expf(-sred[0]));
    }
}

// ---------------------------------------------------------------------------
// fp32 -> bf16 hi/lo split (hidden only: 8MB, ~4us)
// ---------------------------------------------------------------------------
__global__ __launch_bounds__(256) void split_kernel(
    const float* __restrict__ src, bf16* __restrict__ hi, bf16* __restrict__ lo, int n4)
{
    for (int i = blockIdx.x * 256 + threadIdx.x; i < n4; i += gridDim.x * 256) {
        float4 v = ((const float4*)src)[i];
        bf16 hx = __float2bfloat16_rn(v.x);
        bf16 hy = __float2bfloat16_rn(v.y);
        bf16 hz = __float2bfloat16_rn(v.z);
        bf16 hw = __float2bfloat16_rn(v.w);
        bf16 lx = __float2bfloat16_rn(v.x - __bfloat162float(hx));
        bf16 ly = __float2bfloat16_rn(v.y - __bfloat162float(hy));
        bf16 lz = __float2bfloat16_rn(v.z - __bfloat162float(hz));
        bf16 lw = __float2bfloat16_rn(v.w - __bfloat162float(hw));
        ((bf162*)hi)[2 * i]     = bf162(hx, hy);
        ((bf162*)hi)[2 * i + 1] = bf162(hz, hw);
        ((bf162*)lo)[2 * i]     = bf162(lx, ly);
        ((bf162*)lo)[2 * i + 1] = bf162(lz, lw);
    }
}

// ---------------------------------------------------------------------------
// helpers
// ---------------------------------------------------------------------------
__device__ __forceinline__ uint32_t smem_u32(const void* p) {
    return (uint32_t)__cvta_generic_to_shared(p);
}
__device__ __forceinline__ void ldsm_x4(uint32_t* r, uint32_t a) {
    asm volatile("ldmatrix.sync.aligned.m8n8.x4.shared.b16 {%0,%1,%2,%3}, [%4];"
                 : "=r"(r[0]), "=r"(r[1]), "=r"(r[2]), "=r"(r[3]) : "r"(a));
}
__device__ __forceinline__ void ldsm_x4_t(uint32_t* r, uint32_t a) {
    asm volatile("ldmatrix.sync.aligned.m8n8.x4.trans.shared.b16 {%0,%1,%2,%3}, [%4];"
                 : "=r"(r[0]), "=r"(r[1]), "=r"(r[2]), "=r"(r[3]) : "r"(a));
}
// NOTE: non-volatile — pure register computation; lets ptxas software-pipeline.
__device__ __forceinline__ void mma16816(float* d, const uint32_t* a, uint32_t b0, uint32_t b1) {
    asm("mma.sync.aligned.m16n8k16.row.col.f32.bf16.bf16.f32 "
        "{%0,%1,%2,%3}, {%4,%5,%6,%7}, {%8,%9}, {%0,%1,%2,%3};"
        : "+f"(d[0]), "+f"(d[1]), "+f"(d[2]), "+f"(d[3])
        : "r"(a[0]), "r"(a[1]), "r"(a[2]), "r"(a[3]), "r"(b0), "r"(b1));
}
__device__ __forceinline__ void split4(const float4& v, uint2& hi, uint2& lo) {
    bf16 h0 = __float2bfloat16_rn(v.x), h1 = __float2bfloat16_rn(v.y);
    bf16 h2 = __float2bfloat16_rn(v.z), h3 = __float2bfloat16_rn(v.w);
    bf162 H0(h0, h1), H1(h2, h3);
    bf162 L0(__float2bfloat16_rn(v.x - __bfloat162float(h0)),
             __float2bfloat16_rn(v.y - __bfloat162float(h1)));
    bf162 L1(__float2bfloat16_rn(v.z - __bfloat162float(h2)),
             __float2bfloat16_rn(v.w - __bfloat162float(h3)));
    hi.x = *reinterpret_cast<uint32_t*>(&H0); hi.y = *reinterpret_cast<uint32_t*>(&H1);
    lo.x = *reinterpret_cast<uint32_t*>(&L0); lo.y = *reinterpret_cast<uint32_t*>(&L1);
}
__device__ __forceinline__ void split2(float a, float b, uint32_t& hi, uint32_t& lo) {
    bf16 h0 = __float2bfloat16_rn(a), h1 = __float2bfloat16_rn(b);
    bf162 H(h0, h1);
    bf162 L(__float2bfloat16_rn(a - __bfloat162float(h0)),
            __float2bfloat16_rn(b - __bfloat162float(h1)));
    hi = *reinterpret_cast<uint32_t*>(&H);
    lo = *reinterpret_cast<uint32_t*>(&L);
}

#define CP16(dst, src) \
    asm volatile("cp.async.cg.shared.global [%0], [%1], 16;" :: "r"(dst), "l"(src) : "memory")
#define CP_COMMIT() asm volatile("cp.async.commit_group;" ::: "memory")
#define CP_WAIT(n)  asm volatile("cp.async.wait_group %0;" :: "n"(n) : "memory")

// ---------------------------------------------------------------------------
// bf16 hi/lo 3-term GEMM. A bf16 hi/lo via cp.async (double buffer).
// B fp32 from gmem, register-staged split -> smem bf16 hi/lo.
// CTA tile M=128 x TILE_N, 256 threads = 8 warps (4m x 2n), warp tile 32 x TILE_N/2.
// mma issue is TERM-MAJOR within each B-fragment group: 4 independent
// accumulators between reuses of the same acc -> breaks the HMMA RAW chain.
// DUAL=1: TILE_N = [gate(TILE_N/2)|up(TILE_N/2)] at col n0 of each matrix.
// EPI: 0 = silu(gate)*up -> bf16 hi/lo; 1 = expert scatter x weight;
//      2 = shared combine (sigmoid gate + contrib -> outF).
// ---------------------------------------------------------------------------
#define ASTRIDE 80
#define ALO_OFF 10240

template<int GATHER, int AEXP, int DUAL, int EPI, int TILE_N>
__global__ void __launch_bounds__(256, 2) mma2_gemm(
    const bf16* __restrict__ Ahi, const bf16* __restrict__ Alo,
    const float* __restrict__ B0, const float* __restrict__ B1,
    bf16* __restrict__ outHi, bf16* __restrict__ outLo,
    float* __restrict__ outF, int K, int Ntot)
{
    constexpr int NW   = TILE_N / 2;
    constexpr int NJ   = NW / 8;
    constexpr int CPT  = TILE_N / 8;
    constexpr int NF4  = CPT / 4;
    constexpr int BSTR = TILE_N * 2 + 16;
    constexpr int BSZ  = 32 * BSTR;
    constexpr int BHI  = 20480;
    constexpr int BLOO = 20480 + BSZ;
    constexpr int STG  = 20480 + 2 * BSZ;

    const int e  = blockIdx.z;
    const int m0 = blockIdx.y * 128;
    const int n0 = blockIdx.x * (DUAL ? NW : TILE_N);
    const int cnt = (GATHER || AEXP) ? g_cnt[e] : T_TOKENS;
    if (m0 >= cnt) return;

    extern __shared__ char db[];
    __shared__ int s_tok[128];

    const int tid  = threadIdx.x;
    const int lane = tid & 31;
    const int warp = tid >> 5;
    const int wm = warp & 3;
    const int wn = warp >> 2;

    if (GATHER && tid < 128) {
        int gm = m0 + tid;
        s_tok[tid] = (gm < cnt) ? g_tok[e * T_TOKENS + gm] : 0;
    }
    __syncthreads();

    // ---- A loader (cp.async): thread -> row tid>>1, 16 k elems at (tid&1)*16 ----
    const int arow_l = tid >> 1;
    size_t arow;
    if (GATHER) arow = (size_t)s_tok[arow_l];
    else        arow = (AEXP ? (size_t)e * T_TOKENS : 0) + m0 + arow_l;
    const bf16* aHiP = Ahi + arow * K + (tid & 1) * 16;
    const bf16* aLoP = Alo + arow * K + (tid & 1) * 16;
    const uint32_t aDst = smem_u32(db) + (uint32_t)(arow_l * ASTRIDE + (tid & 1) * 32);

    auto issueA = [&](int k0, int s) {
        const uint32_t so = (uint32_t)(s * STG);
        CP16(aDst + so,      aHiP + k0);
        CP16(aDst + so + 16, aHiP + k0 + 8);
        CP16(aDst + so + ALO_OFF,      aLoP + k0);
        CP16(aDst + so + ALO_OFF + 16, aLoP + k0 + 8);
    };

    // ---- B loader (fp32 LDG + split): k-row tid>>3, CPT cols at (tid&7)*CPT ----
    const int bkr = tid >> 3;
    const int seg = (tid & 7) * CPT;
    const size_t eoff = (GATHER || AEXP) ? (size_t)e * K * Ntot : 0;
    const float* BP;
    if (DUAL) BP = (seg < NW ? B0 + eoff + n0 + seg : B1 + eoff + n0 + seg - NW);
    else      BP = B0 + eoff + n0 + seg;
    BP += (size_t)bkr * Ntot;
    const uint32_t bOff = (uint32_t)(bkr * BSTR + seg * 2);

    float4 pb[NF4];
    auto ldgB = [&](int k0) {
        const float4* p = (const float4*)(BP + (size_t)k0 * Ntot);
        #pragma unroll
        for (int i = 0; i < NF4; ++i) pb[i] = p[i];
    };
    auto stsB = [&](int s) {
        char* st = db + s * STG;
        #pragma unroll
        for (int i = 0; i < NF4 / 2; ++i) {
            uint2 h0, l0, h1, l1;
            split4(pb[2 * i], h0, l0); split4(pb[2 * i + 1], h1, l1);
            *(uint4*)(st + BHI  + bOff + i * 16) = make_uint4(h0.x, h0.y, h1.x, h1.y);
            *(uint4*)(st + BLOO + bOff + i * 16) = make_uint4(l0.x, l0.y, l1.x, l1.y);
        }
    };

    float acc[2][NJ][4];
    #pragma unroll
    for (int i = 0; i < 2; ++i)
        #pragma unroll
        for (int j = 0; j < NJ; ++j)
            #pragma unroll
            for (int v = 0; v < 4; ++v) acc[i][j][v] = 0.f;

    const int grp = lane >> 3;
    const int gl  = lane & 7;
    const int a_row_off = (grp & 1) * 8 + gl;
    const int a_col_off = (grp >> 1) * 8;
    const int b_row_off = (grp & 1) * 8 + gl;
    const int b_col_off = (grp >> 1) * 8;

    const int C = K / 32;
    ldgB(0);
    issueA(0, 0);
    CP_COMMIT();

    for (int c = 0; c < C; ++c) {
        if (c + 1 < C) {
            issueA((c + 1) * 32, (c + 1) & 1);
            CP_COMMIT();
            CP_WAIT(1);
        } else {
            CP_WAIT(0);
        }
        stsB(c & 1);
        if (c + 1 < C) ldgB((c + 1) * 32);
        __syncthreads();

        const uint32_t base = smem_u32(db) + (uint32_t)((c & 1) * STG);
        #pragma unroll
        for (int ks = 0; ks < 32; ks += 16) {
            uint32_t ah[2][4], al[2][4];
            #pragma unroll
            for (int mi = 0; mi < 2; ++mi) {
                const uint32_t ra = base + (uint32_t)((wm * 32 + mi * 16 + a_row_off) * ASTRIDE + (ks + a_col_off) * 2);
                ldsm_x4(ah[mi], ra);
                ldsm_x4(al[mi], ra + ALO_OFF);
            }
            #pragma unroll
            for (int g = 0; g < NW / 16; ++g) {
                uint32_t bh[4], bl[4];
                const uint32_t rb = base + (uint32_t)(BHI + (ks + b_row_off) * BSTR + (wn * NW + g * 16 + b_col_off) * 2);
                ldsm_x4_t(bh, rb);
                ldsm_x4_t(bl, rb + BSZ);
                // term-major: 4 independent accumulators between acc reuses
                #pragma unroll
                for (int mi = 0; mi < 2; ++mi)
                    #pragma unroll
                    for (int half = 0; half < 2; ++half)
                        mma16816(acc[mi][g * 2 + half], ah[mi], bh[half * 2], bh[half * 2 + 1]);
                #pragma unroll
                for (int mi = 0; mi < 2; ++mi)
                    #pragma unroll
                    for (int half = 0; half < 2; ++half)
                        mma16816(acc[mi][g * 2 + half], ah[mi], bl[half * 2], bl[half * 2 + 1]);
                #pragma unroll
                for (int mi = 0; mi < 2; ++mi)
                    #pragma unroll
                    for (int half = 0; half < 2; ++half)
                        mma16816(acc[mi][g * 2 + half], al[mi], bh[half * 2], bh[half * 2 + 1]);
            }
        }
        __syncthreads();
    }

    // ---- epilogues ----
    if (EPI == 0) {
        constexpr int EXS = NW + 8;
        float* exch = (float*)db;
        if (wn == 1) {
            #pragma unroll
            for (int mi = 0; mi < 2; ++mi)
                #pragma unroll
                for (int nj = 0; nj < NJ; ++nj) {
                    const int cl = nj * 8 + (lane & 3) * 2;
                    #pragma unroll
                    for (int h = 0; h < 2; ++h) {
                        const int rl = wm * 32 + mi * 16 + (lane >> 2) + h * 8;
                        exch[rl * EXS + cl]     = acc[mi][nj][h * 2];
                        exch[rl * EXS + cl + 1] = acc[mi][nj][h * 2 + 1];
                    }
                }
        }
        __syncthreads();
        if (wn == 0) {
            #pragma unroll
            for (int mi = 0; mi < 2; ++mi)
                #pragma unroll
                for (int h = 0; h < 2; ++h) {
                    const int rl = wm * 32 + mi * 16 + (lane >> 2) + h * 8;
                    const int r = m0 + rl;
                    if (GATHER && r >= cnt) continue;
                    const size_t row = (GATHER ? (size_t)e * T_TOKENS : 0) + r;
                    #pragma unroll
                    for (int nj = 0; nj < NJ; ++nj) {
                        const int cl = nj * 8 + (lane & 3) * 2;
                        const float g0 = acc[mi][nj][h * 2];
                        const float g1 = acc[mi][nj][h * 2 + 1];
                        const float u0 = exch[rl * EXS + cl];
                        const float u1 = exch[rl * EXS + cl + 1];
                        const float a0 = (g0 / (1.f + expf(-g0))) * u0;
                        const float a1 = (g1 / (1.f + expf(-g1))) * u1;
                        uint32_t hi, lo; split2(a0, a1, hi, lo);
                        *(uint32_t*)(outHi + row * Ntot + n0 + cl) = hi;
                        *(uint32_t*)(outLo + row * Ntot + n0 + cl) = lo;
                    }
                }
        }
    } else {
        #pragma unroll
        for (int mi = 0; mi < 2; ++mi)
            #pragma unroll
            for (int h = 0; h < 2; ++h) {
                const int rl = wm * 32 + mi * 16 + (lane >> 2) + h * 8;
                const int r = m0 + rl;
                if (EPI == 1) {
                    if (r >= cnt) continue;
                    const int idx = e * T_TOKENS + r;
                    const float w = g_wt[idx];
                    float* orow = g_contrib + ((size_t)g_tok[idx] * 2 + g_slot[idx]) * H_DIM;
                    #pragma unroll
                    for (int nj = 0; nj < NJ; ++nj) {
                        const int c = n0 + wn * NW + nj * 8 + (lane & 3) * 2;
                        float2 o = {acc[mi][nj][h * 2] * w, acc[mi][nj][h * 2 + 1] * w};
                        *(float2*)(orow + c) = o;
                    }
                } else {
                    const float sg = g_sgate[r];
                    #pragma unroll
                    for (int nj = 0; nj < NJ; ++nj) {
                        const int c = n0 + wn * NW + nj * 8 + (lane & 3) * 2;
                        const float2 c0 = *(const float2*)(g_contrib + ((size_t)r * 2 + 0) * H_DIM + c);
                        const float2 c1 = *(const float2*)(g_contrib + ((size_t)r * 2 + 1) * H_DIM + c);
                        float2 o = {sg * acc[mi][nj][h * 2] + c0.x + c1.x,
                                    sg * acc[mi][nj][h * 2 + 1] + c0.y + c1.y};
                        *(float2*)(outF + (size_t)r * H_DIM + c) = o;
                    }
                }
            }
    }
}

// ---------------------------------------------------------------------------
extern "C" void kernel_launch(void* const* d_in, const int* in_sizes, int n_in,
                              void* d_out, int out_size)
{
    const float* hidden        = (const float*)d_in[0];
    const float* gate_w        = (const float*)d_in[1];
    const float* w_gate        = (const float*)d_in[2];
    const float* w_up          = (const float*)d_in[3];
    const float* w_down        = (const float*)d_in[4];
    const float* sw_gate       = (const float*)d_in[5];
    const float* sw_up         = (const float*)d_in[6];
    const float* sw_down       = (const float*)d_in[7];
    const float* shared_gate_w = (const float*)d_in[8];

    float* out        = (float*)d_out;
    float* out_logits = out + (size_t)T_TOKENS * H_DIM;

    bf16 *hidHi, *hidLo, *actHi, *actLo, *shHi, *shLo;
    cudaGetSymbolAddress((void**)&hidHi, g_hid_hi);  cudaGetSymbolAddress((void**)&hidLo, g_hid_lo);
    cudaGetSymbolAddress((void**)&actHi, g_act_hi);  cudaGetSymbolAddress((void**)&actLo, g_act_lo);
    cudaGetSymbolAddress((void**)&shHi, g_shact_hi); cudaGetSymbolAddress((void**)&shLo, g_shact_lo);

    const int SM128 = 2 * (20480 + 2 * (32 * (128 * 2 + 16)));

    cudaFuncSetAttribute(mma2_gemm<1,0,1,0,128>, cudaFuncAttributeMaxDynamicSharedMemorySize, SM128);
    cudaFuncSetAttribute(mma2_gemm<0,1,0,1,128>, cudaFuncAttributeMaxDynamicSharedMemorySize, SM128);
    cudaFuncSetAttribute(mma2_gemm<0,0,1,0,128>, cudaFuncAttributeMaxDynamicSharedMemorySize, SM128);
    cudaFuncSetAttribute(mma2_gemm<0,0,0,2,128>, cudaFuncAttributeMaxDynamicSharedMemorySize, SM128);

    zero_cnt_kernel<<<1, 32>>>();
    router_kernel<<<T_TOKENS, 256>>>(hidden, gate_w, shared_gate_w, out_logits);

    // hidden split only (8MB, ~4us)
    {
        int n4 = (int)((size_t)T_TOKENS * H_DIM / 4);
        split_kernel<<<(n4 + 255) / 256, 256>>>(hidden, hidHi, hidLo, n4);
    }

    // expert gate+up -> act hi/lo (R10 config: 64 cols per matrix per CTA)
    mma2_gemm<1,0,1,0,128><<<dim3(I_DIM / 64, T_TOKENS / 128, NE), 256, SM128>>>(
        hidHi, hidLo, w_gate, w_up, actHi, actLo, nullptr, H_DIM, I_DIM);
    // expert down -> contrib scatter
    mma2_gemm<0,1,0,1,128><<<dim3(H_DIM / 128, T_TOKENS / 128, NE), 256, SM128>>>(
        actHi, actLo, w_down, w_down, nullptr, nullptr, nullptr, I_DIM, H_DIM);
    // shared gate+up -> shact hi/lo
    mma2_gemm<0,0,1,0,128><<<dim3(SI_DIM / 64, T_TOKENS / 128, 1), 256, SM128>>>(
        hidHi, hidLo, sw_gate, sw_up, shHi, shLo, nullptr, H_DIM, SI_DIM);
    // shared down + combine -> out
    mma2_gemm<0,0,0,2,128><<<dim3(H_DIM / 128, T_TOKENS / 128, 1), 256, SM128>>>(
        shHi, shLo, sw_down, sw_down, nullptr, nullptr, out, SI_DIM, H_DIM);
}

// round 13
// speedup vs baseline: 1.2884x; 1.2061x over previous
#include <cuda_runtime.h>
#include <cuda_fp16.h>
#include <math.h>
#include <stdint.h>

#define T_TOKENS 1024
#define H_DIM    2048
#define I_DIM    1408
#define SI_DIM   5632
#define NE       8

// ---------------------------------------------------------------------------
// Scratch (__device__ globals; no cudaMalloc allowed)
// ---------------------------------------------------------------------------
__device__ int   g_cnt[NE];
__device__ int   g_tok [NE * T_TOKENS];
__device__ int   g_slot[NE * T_TOKENS];
__device__ float g_wt  [NE * T_TOKENS];
__device__ float g_sgate[T_TOKENS];

__device__ __half g_hid_hi[(size_t)T_TOKENS * H_DIM];
__device__ __half g_hid_lo[(size_t)T_TOKENS * H_DIM];

__device__ __half g_act_hi[(size_t)NE * T_TOKENS * I_DIM];
__device__ __half g_act_lo[(size_t)NE * T_TOKENS * I_DIM];
__device__ __half g_shact_hi[(size_t)T_TOKENS * SI_DIM];
__device__ __half g_shact_lo[(size_t)T_TOKENS * SI_DIM];
__device__ float  g_contrib[(size_t)T_TOKENS * 2 * H_DIM];

// ---------------------------------------------------------------------------
__global__ void zero_cnt_kernel() {
    if (threadIdx.x < NE) g_cnt[threadIdx.x] = 0;
}

__global__ __launch_bounds__(256) void router_kernel(
    const float* __restrict__ hidden,
    const float* __restrict__ gate_w,
    const float* __restrict__ shared_gate_w,
    float* __restrict__ out_logits)
{
    const int t = blockIdx.x;
    __shared__ float sh[H_DIM];
    __shared__ float slog[NE];
    __shared__ float sred[256];

    const float* hrow = hidden + (size_t)t * H_DIM;
    for (int i = threadIdx.x; i < H_DIM; i += 256) sh[i] = hrow[i];
    __syncthreads();

    const int warp = threadIdx.x >> 5;
    const int lane = threadIdx.x & 31;

    float sum = 0.f;
    for (int k = lane; k < H_DIM; k += 32) sum += sh[k] * gate_w[k * NE + warp];
    #pragma unroll
    for (int o = 16; o; o >>= 1) sum += __shfl_down_sync(0xffffffffu, sum, o);
    if (lane == 0) slog[warp] = sum;

    float s2 = 0.f;
    for (int k = threadIdx.x; k < H_DIM; k += 256) s2 += sh[k] * shared_gate_w[k];
    sred[threadIdx.x] = s2;
    __syncthreads();
    for (int st = 128; st; st >>= 1) {
        if (threadIdx.x < st) sred[threadIdx.x] += sred[threadIdx.x + st];
        __syncthreads();
    }

    if (threadIdx.x == 0) {
        float lg[NE];
        float mx = -1e30f;
        #pragma unroll
        for (int e = 0; e < NE; ++e) { lg[e] = slog[e]; mx = fmaxf(mx, lg[e]); }
        float p[NE]; float den = 0.f;
        #pragma unroll
        for (int e = 0; e < NE; ++e) { p[e] = expf(lg[e] - mx); den += p[e]; }
        float inv = 1.f / den;
        #pragma unroll
        for (int e = 0; e < NE; ++e) {
            p[e] *= inv;
            out_logits[(size_t)t * NE + e] = lg[e];
        }
        int i0 = 0;
        #pragma unroll
        for (int e = 1; e < NE; ++e) if (p[e] > p[i0]) i0 = e;
        int i1 = -1;
        #pragma unroll
        for (int e = 0; e < NE; ++e) {
            if (e == i0) continue;
            if (i1 < 0 || p[e] > p[i1]) i1 = e;
        }
        int pos0 = atomicAdd(&g_cnt[i0], 1);
        g_tok [i0 * T_TOKENS + pos0] = t;
        g_slot[i0 * T_TOKENS + pos0] = 0;
        g_wt  [i0 * T_TOKENS + pos0] = p[i0];
        int pos1 = atomicAdd(&g_cnt[i1], 1);
        g_tok [i1 * T_TOKENS + pos1] = t;
        g_slot[i1 * T_TOKENS + pos1] = 1;
        g_wt  [i1 * T_TOKENS + pos1] = p[i1];

        g_sgate[t] = 1.f / (1.f + expf(-sred[0]));
    }
}

// ---------------------------------------------------------------------------
// fp32 -> fp16 hi/lo split (hidden only: 8MB, ~4us)
// ---------------------------------------------------------------------------
__global__ __launch_bounds__(256) void split_kernel(
    const float* __restrict__ src, __half* __restrict__ hi, __half* __restrict__ lo, int n4)
{
    for (int i = blockIdx.x * 256 + threadIdx.x; i < n4; i += gridDim.x * 256) {
        float4 v = ((const float4*)src)[i];
        __half hx = __float2half_rn(v.x);
        __half hy = __float2half_rn(v.y);
        __half hz = __float2half_rn(v.z);
        __half hw = __float2half_rn(v.w);
        __half lx = __float2half_rn(v.x - __half2float(hx));
        __half ly = __float2half_rn(v.y - __half2float(hy));
        __half lz = __float2half_rn(v.z - __half2float(hz));
        __half lw = __float2half_rn(v.w - __half2float(hw));
        ((__half2*)hi)[2 * i]     = __halves2half2(hx, hy);
        ((__half2*)hi)[2 * i + 1] = __halves2half2(hz, hw);
        ((__half2*)lo)[2 * i]     = __halves2half2(lx, ly);
        ((__half2*)lo)[2 * i + 1] = __halves2half2(lz, lw);
    }
}

// ---------------------------------------------------------------------------
// helpers
// ---------------------------------------------------------------------------
__device__ __forceinline__ uint32_t smem_u32(const void* p) {
    return (uint32_t)__cvta_generic_to_shared(p);
}
__device__ __forceinline__ void ldsm_x4(uint32_t* r, uint32_t a) {
    asm volatile("ldmatrix.sync.aligned.m8n8.x4.shared.b16 {%0,%1,%2,%3}, [%4];"
                 : "=r"(r[0]), "=r"(r[1]), "=r"(r[2]), "=r"(r[3]) : "r"(a));
}
__device__ __forceinline__ void ldsm_x4_t(uint32_t* r, uint32_t a) {
    asm volatile("ldmatrix.sync.aligned.m8n8.x4.trans.shared.b16 {%0,%1,%2,%3}, [%4];"
                 : "=r"(r[0]), "=r"(r[1]), "=r"(r[2]), "=r"(r[3]) : "r"(a));
}
// fp16 mma, fp32 accumulate; non-volatile (pure register computation)
__device__ __forceinline__ void mma16816(float* d, const uint32_t* a, uint32_t b0, uint32_t b1) {
    asm("mma.sync.aligned.m16n8k16.row.col.f32.f16.f16.f32 "
        "{%0,%1,%2,%3}, {%4,%5,%6,%7}, {%8,%9}, {%0,%1,%2,%3};"
        : "+f"(d[0]), "+f"(d[1]), "+f"(d[2]), "+f"(d[3])
        : "r"(a[0]), "r"(a[1]), "r"(a[2]), "r"(a[3]), "r"(b0), "r"(b1));
}
__device__ __forceinline__ uint32_t h2bits(__half2 h) {
    return *reinterpret_cast<uint32_t*>(&h);
}
__device__ __forceinline__ void split2h(float a, float b, uint32_t& hi, uint32_t& lo) {
    __half ha = __float2half_rn(a), hb = __float2half_rn(b);
    hi = h2bits(__halves2half2(ha, hb));
    lo = h2bits(__halves2half2(__float2half_rn(a - __half2float(ha)),
                               __float2half_rn(b - __half2float(hb))));
}

#define CP16(dst, src) \
    asm volatile("cp.async.cg.shared.global [%0], [%1], 16;" :: "r"(dst), "l"(src) : "memory")
#define CP_COMMIT() asm volatile("cp.async.commit_group;" ::: "memory")
#define CP_WAIT(n)  asm volatile("cp.async.wait_group %0;" :: "n"(n) : "memory")

// ---------------------------------------------------------------------------
// fp16 2-term GEMM: C = (Ahi + Alo) x B_fp16, fp32 accumulate.
// A fp16 hi/lo via cp.async (double buffer). B fp32 from gmem, converted to
// single-rounded fp16 in registers -> smem.
// CTA tile M=128 x TILE_N, 256 threads = 8 warps (4m x 2n), warp tile 32 x TILE_N/2.
// DUAL=1: TILE_N = [gate(TILE_N/2)|up(TILE_N/2)] at col n0 of each matrix.
// EPI: 0 = silu(gate)*up -> fp16 hi/lo; 1 = expert scatter x weight;
//      2 = shared combine (sigmoid gate + contrib -> outF).
// ---------------------------------------------------------------------------
#define ASTRIDE 80
#define ALO_OFF 10240

template<int GATHER, int AEXP, int DUAL, int EPI, int TILE_N>
__global__ void __launch_bounds__(256, 2) mma2_gemm(
    const __half* __restrict__ Ahi, const __half* __restrict__ Alo,
    const float* __restrict__ B0, const float* __restrict__ B1,
    __half* __restrict__ outHi, __half* __restrict__ outLo,
    float* __restrict__ outF, int K, int Ntot)
{
    constexpr int NW   = TILE_N / 2;
    constexpr int NJ   = NW / 8;
    constexpr int CPT  = TILE_N / 8;
    constexpr int NF4  = CPT / 4;
    constexpr int BSTR = TILE_N * 2 + 16;
    constexpr int BSZ  = 32 * BSTR;
    constexpr int BHI  = 20480;
    constexpr int STG  = 20480 + BSZ;

    const int e  = blockIdx.z;
    const int m0 = blockIdx.y * 128;
    const int n0 = blockIdx.x * (DUAL ? NW : TILE_N);
    const int cnt = (GATHER || AEXP) ? g_cnt[e] : T_TOKENS;
    if (m0 >= cnt) return;

    extern __shared__ char db[];
    __shared__ int s_tok[128];

    const int tid  = threadIdx.x;
    const int lane = tid & 31;
    const int warp = tid >> 5;
    const int wm = warp & 3;
    const int wn = warp >> 2;

    if (GATHER && tid < 128) {
        int gm = m0 + tid;
        s_tok[tid] = (gm < cnt) ? g_tok[e * T_TOKENS + gm] : 0;
    }
    __syncthreads();

    // ---- A loader (cp.async): thread -> row tid>>1, 16 k elems at (tid&1)*16 ----
    const int arow_l = tid >> 1;
    size_t arow;
    if (GATHER) arow = (size_t)s_tok[arow_l];
    else        arow = (AEXP ? (size_t)e * T_TOKENS : 0) + m0 + arow_l;
    const __half* aHiP = Ahi + arow * K + (tid & 1) * 16;
    const __half* aLoP = Alo + arow * K + (tid & 1) * 16;
    const uint32_t aDst = smem_u32(db) + (uint32_t)(arow_l * ASTRIDE + (tid & 1) * 32);

    auto issueA = [&](int k0, int s) {
        const uint32_t so = (uint32_t)(s * STG);
        CP16(aDst + so,      aHiP + k0);
        CP16(aDst + so + 16, aHiP + k0 + 8);
        CP16(aDst + so + ALO_OFF,      aLoP + k0);
        CP16(aDst + so + ALO_OFF + 16, aLoP + k0 + 8);
    };

    // ---- B loader (fp32 LDG -> fp16 in regs -> smem): k-row tid>>3, CPT cols ----
    const int bkr = tid >> 3;
    const int seg = (tid & 7) * CPT;
    const size_t eoff = (GATHER || AEXP) ? (size_t)e * K * Ntot : 0;
    const float* BP;
    if (DUAL) BP = (seg < NW ? B0 + eoff + n0 + seg : B1 + eoff + n0 + seg - NW);
    else      BP = B0 + eoff + n0 + seg;
    BP += (size_t)bkr * Ntot;
    const uint32_t bOff = (uint32_t)(bkr * BSTR + seg * 2);

    float4 pb[NF4];
    auto ldgB = [&](int k0) {
        const float4* p = (const float4*)(BP + (size_t)k0 * Ntot);
        #pragma unroll
        for (int i = 0; i < NF4; ++i) pb[i] = p[i];
    };
    auto stsB = [&](int s) {
        char* st = db + s * STG;
        #pragma unroll
        for (int i = 0; i < NF4 / 2; ++i) {
            const uint32_t u0 = h2bits(__floats2half2_rn(pb[2 * i].x,     pb[2 * i].y));
            const uint32_t u1 = h2bits(__floats2half2_rn(pb[2 * i].z,     pb[2 * i].w));
            const uint32_t u2 = h2bits(__floats2half2_rn(pb[2 * i + 1].x, pb[2 * i + 1].y));
            const uint32_t u3 = h2bits(__floats2half2_rn(pb[2 * i + 1].z, pb[2 * i + 1].w));
            *(uint4*)(st + BHI + bOff + i * 16) = make_uint4(u0, u1, u2, u3);
        }
    };

    float acc[2][NJ][4];
    #pragma unroll
    for (int i = 0; i < 2; ++i)
        #pragma unroll
        for (int j = 0; j < NJ; ++j)
            #pragma unroll
            for (int v = 0; v < 4; ++v) acc[i][j][v] = 0.f;

    const int grp = lane >> 3;
    const int gl  = lane & 7;
    const int a_row_off = (grp & 1) * 8 + gl;
    const int a_col_off = (grp >> 1) * 8;
    const int b_row_off = (grp & 1) * 8 + gl;
    const int b_col_off = (grp >> 1) * 8;

    const int C = K / 32;
    ldgB(0);
    issueA(0, 0);
    CP_COMMIT();

    for (int c = 0; c < C; ++c) {
        if (c + 1 < C) {
            issueA((c + 1) * 32, (c + 1) & 1);
            CP_COMMIT();
            CP_WAIT(1);
        } else {
            CP_WAIT(0);
        }
        stsB(c & 1);
        if (c + 1 < C) ldgB((c + 1) * 32);
        __syncthreads();

        const uint32_t base = smem_u32(db) + (uint32_t)((c & 1) * STG);
        #pragma unroll
        for (int ks = 0; ks < 32; ks += 16) {
            uint32_t ah[2][4], al[2][4];
            #pragma unroll
            for (int mi = 0; mi < 2; ++mi) {
                const uint32_t ra = base + (uint32_t)((wm * 32 + mi * 16 + a_row_off) * ASTRIDE + (ks + a_col_off) * 2);
                ldsm_x4(ah[mi], ra);
                ldsm_x4(al[mi], ra + ALO_OFF);
            }
            #pragma unroll
            for (int g = 0; g < NW / 16; ++g) {
                uint32_t bh[4];
                const uint32_t rb = base + (uint32_t)(BHI + (ks + b_row_off) * BSTR + (wn * NW + g * 16 + b_col_off) * 2);
                ldsm_x4_t(bh, rb);
                // term-major: 4 independent accumulators between acc reuses
                #pragma unroll
                for (int mi = 0; mi < 2; ++mi)
                    #pragma unroll
                    for (int half = 0; half < 2; ++half)
                        mma16816(acc[mi][g * 2 + half], ah[mi], bh[half * 2], bh[half * 2 + 1]);
                #pragma unroll
                for (int mi = 0; mi < 2; ++mi)
                    #pragma unroll
                    for (int half = 0; half < 2; ++half)
                        mma16816(acc[mi][g * 2 + half], al[mi], bh[half * 2], bh[half * 2 + 1]);
            }
        }
        __syncthreads();
    }

    // ---- epilogues ----
    if (EPI == 0) {
        constexpr int EXS = NW + 8;
        float* exch = (float*)db;
        if (wn == 1) {
            #pragma unroll
            for (int mi = 0; mi < 2; ++mi)
                #pragma unroll
                for (int nj = 0; nj < NJ; ++nj) {
                    const int cl = nj * 8 + (lane & 3) * 2;
                    #pragma unroll
                    for (int h = 0; h < 2; ++h) {
                        const int rl = wm * 32 + mi * 16 + (lane >> 2) + h * 8;
                        exch[rl * EXS + cl]     = acc[mi][nj][h * 2];
                        exch[rl * EXS + cl + 1] = acc[mi][nj][h * 2 + 1];
                    }
                }
        }
        __syncthreads();
        if (wn == 0) {
            #pragma unroll
            for (int mi = 0; mi < 2; ++mi)
                #pragma unroll
                for (int h = 0; h < 2; ++h) {
                    const int rl = wm * 32 + mi * 16 + (lane >> 2) + h * 8;
                    const int r = m0 + rl;
                    if (GATHER && r >= cnt) continue;
                    const size_t row = (GATHER ? (size_t)e * T_TOKENS : 0) + r;
                    #pragma unroll
                    for (int nj = 0; nj < NJ; ++nj) {
                        const int cl = nj * 8 + (lane & 3) * 2;
                        const float g0 = acc[mi][nj][h * 2];
                        const float g1 = acc[mi][nj][h * 2 + 1];
                        const float u0 = exch[rl * EXS + cl];
                        const float u1 = exch[rl * EXS + cl + 1];
                        const float a0 = (g0 / (1.f + expf(-g0))) * u0;
                        const float a1 = (g1 / (1.f + expf(-g1))) * u1;
                        uint32_t hi, lo; split2h(a0, a1, hi, lo);
                        *(uint32_t*)(outHi + row * Ntot + n0 + cl) = hi;
                        *(uint32_t*)(outLo + row * Ntot + n0 + cl) = lo;
                    }
                }
        }
    } else {
        #pragma unroll
        for (int mi = 0; mi < 2; ++mi)
            #pragma unroll
            for (int h = 0; h < 2; ++h) {
                const int rl = wm * 32 + mi * 16 + (lane >> 2) + h * 8;
                const int r = m0 + rl;
                if (EPI == 1) {
                    if (r >= cnt) continue;
                    const int idx = e * T_TOKENS + r;
                    const float w = g_wt[idx];
                    float* orow = g_contrib + ((size_t)g_tok[idx] * 2 + g_slot[idx]) * H_DIM;
                    #pragma unroll
                    for (int nj = 0; nj < NJ; ++nj) {
                        const int c = n0 + wn * NW + nj * 8 + (lane & 3) * 2;
                        float2 o = {acc[mi][nj][h * 2] * w, acc[mi][nj][h * 2 + 1] * w};
                        *(float2*)(orow + c) = o;
                    }
                } else {
                    const float sg = g_sgate[r];
                    #pragma unroll
                    for (int nj = 0; nj < NJ; ++nj) {
                        const int c = n0 + wn * NW + nj * 8 + (lane & 3) * 2;
                        const float2 c0 = *(const float2*)(g_contrib + ((size_t)r * 2 + 0) * H_DIM + c);
                        const float2 c1 = *(const float2*)(g_contrib + ((size_t)r * 2 + 1) * H_DIM + c);
                        float2 o = {sg * acc[mi][nj][h * 2] + c0.x + c1.x,
                                    sg * acc[mi][nj][h * 2 + 1] + c0.y + c1.y};
                        *(float2*)(outF + (size_t)r * H_DIM + c) = o;
                    }
                }
            }
    }
}

// ---------------------------------------------------------------------------
extern "C" void kernel_launch(void* const* d_in, const int* in_sizes, int n_in,
                              void* d_out, int out_size)
{
    const float* hidden        = (const float*)d_in[0];
    const float* gate_w        = (const float*)d_in[1];
    const float* w_gate        = (const float*)d_in[2];
    const float* w_up          = (const float*)d_in[3];
    const float* w_down        = (const float*)d_in[4];
    const float* sw_gate       = (const float*)d_in[5];
    const float* sw_up         = (const float*)d_in[6];
    const float* sw_down       = (const float*)d_in[7];
    const float* shared_gate_w = (const float*)d_in[8];

    float* out        = (float*)d_out;
    float* out_logits = out + (size_t)T_TOKENS * H_DIM;

    __half *hidHi, *hidLo, *actHi, *actLo, *shHi, *shLo;
    cudaGetSymbolAddress((void**)&hidHi, g_hid_hi);  cudaGetSymbolAddress((void**)&hidLo, g_hid_lo);
    cudaGetSymbolAddress((void**)&actHi, g_act_hi);  cudaGetSymbolAddress((void**)&actLo, g_act_lo);
    cudaGetSymbolAddress((void**)&shHi, g_shact_hi); cudaGetSymbolAddress((void**)&shLo, g_shact_lo);

    // stage = A(20480) + B(32*(128*2+16)=8704) = 29184; double buffered = 58368
    const int SM128 = 2 * (20480 + 32 * (128 * 2 + 16));

    cudaFuncSetAttribute(mma2_gemm<1,0,1,0,128>, cudaFuncAttributeMaxDynamicSharedMemorySize, SM128);
    cudaFuncSetAttribute(mma2_gemm<0,1,0,1,128>, cudaFuncAttributeMaxDynamicSharedMemorySize, SM128);
    cudaFuncSetAttribute(mma2_gemm<0,0,1,0,128>, cudaFuncAttributeMaxDynamicSharedMemorySize, SM128);
    cudaFuncSetAttribute(mma2_gemm<0,0,0,2,128>, cudaFuncAttributeMaxDynamicSharedMemorySize, SM128);

    zero_cnt_kernel<<<1, 32>>>();
    router_kernel<<<T_TOKENS, 256>>>(hidden, gate_w, shared_gate_w, out_logits);

    // hidden split only (8MB, ~4us)
    {
        int n4 = (int)((size_t)T_TOKENS * H_DIM / 4);
        split_kernel<<<(n4 + 255) / 256, 256>>>(hidden, hidHi, hidLo, n4);
    }

    // expert gate+up -> act hi/lo
    mma2_gemm<1,0,1,0,128><<<dim3(I_DIM / 64, T_TOKENS / 128, NE), 256, SM128>>>(
        hidHi, hidLo, w_gate, w_up, actHi, actLo, nullptr, H_DIM, I_DIM);
    // expert down -> contrib scatter
    mma2_gemm<0,1,0,1,128><<<dim3(H_DIM / 128, T_TOKENS / 128, NE), 256, SM128>>>(
        actHi, actLo, w_down, w_down, nullptr, nullptr, nullptr, I_DIM, H_DIM);
    // shared gate+up -> shact hi/lo
    mma2_gemm<0,0,1,0,128><<<dim3(SI_DIM / 64, T_TOKENS / 128, 1), 256, SM128>>>(
        hidHi, hidLo, sw_gate, sw_up, shHi, shLo, nullptr, H_DIM, SI_DIM);
    // shared down + combine -> out
    mma2_gemm<0,0,0,2,128><<<dim3(H_DIM / 128, T_TOKENS / 128, 1), 256, SM128>>>(
        shHi, shLo, sw_down, sw_down, nullptr, nullptr, out, SI_DIM, H_DIM);
}

// round 14
// speedup vs baseline: 1.3911x; 1.0797x over previous
#include <cuda_runtime.h>
#include <cuda_fp16.h>
#include <math.h>
#include <stdint.h>

#define T_TOKENS 1024
#define H_DIM    2048
#define I_DIM    1408
#define SI_DIM   5632
#define NE       8

// ---------------------------------------------------------------------------
// Scratch (__device__ globals; no cudaMalloc allowed)
// ---------------------------------------------------------------------------
__device__ int   g_cnt[NE];
__device__ int   g_tok [NE * T_TOKENS];
__device__ int   g_slot[NE * T_TOKENS];
__device__ float g_wt  [NE * T_TOKENS];
__device__ float g_sgate[T_TOKENS];

__device__ __half g_hid_hi[(size_t)T_TOKENS * H_DIM];
__device__ __half g_hid_lo[(size_t)T_TOKENS * H_DIM];

__device__ __half g_act_hi[(size_t)NE * T_TOKENS * I_DIM];
__device__ __half g_act_lo[(size_t)NE * T_TOKENS * I_DIM];
__device__ __half g_shact_hi[(size_t)T_TOKENS * SI_DIM];
__device__ __half g_shact_lo[(size_t)T_TOKENS * SI_DIM];
__device__ float  g_contrib[(size_t)T_TOKENS * 2 * H_DIM];

// ---------------------------------------------------------------------------
__global__ void zero_cnt_kernel() {
    if (threadIdx.x < NE) g_cnt[threadIdx.x] = 0;
}

__global__ __launch_bounds__(256) void router_kernel(
    const float* __restrict__ hidden,
    const float* __restrict__ gate_w,
    const float* __restrict__ shared_gate_w,
    float* __restrict__ out_logits)
{
    const int t = blockIdx.x;
    __shared__ float sh[H_DIM];
    __shared__ float slog[NE];
    __shared__ float sred[256];

    const float* hrow = hidden + (size_t)t * H_DIM;
    for (int i = threadIdx.x; i < H_DIM; i += 256) sh[i] = hrow[i];
    __syncthreads();

    const int warp = threadIdx.x >> 5;
    const int lane = threadIdx.x & 31;

    float sum = 0.f;
    for (int k = lane; k < H_DIM; k += 32) sum += sh[k] * gate_w[k * NE + warp];
    #pragma unroll
    for (int o = 16; o; o >>= 1) sum += __shfl_down_sync(0xffffffffu, sum, o);
    if (lane == 0) slog[warp] = sum;

    float s2 = 0.f;
    for (int k = threadIdx.x; k < H_DIM; k += 256) s2 += sh[k] * shared_gate_w[k];
    sred[threadIdx.x] = s2;
    __syncthreads();
    for (int st = 128; st; st >>= 1) {
        if (threadIdx.x < st) sred[threadIdx.x] += sred[threadIdx.x + st];
        __syncthreads();
    }

    if (threadIdx.x == 0) {
        float lg[NE];
        float mx = -1e30f;
        #pragma unroll
        for (int e = 0; e < NE; ++e) { lg[e] = slog[e]; mx = fmaxf(mx, lg[e]); }
        float p[NE]; float den = 0.f;
        #pragma unroll
        for (int e = 0; e < NE; ++e) { p[e] = expf(lg[e] - mx); den += p[e]; }
        float inv = 1.f / den;
        #pragma unroll
        for (int e = 0; e < NE; ++e) {
            p[e] *= inv;
            out_logits[(size_t)t * NE + e] = lg[e];
        }
        int i0 = 0;
        #pragma unroll
        for (int e = 1; e < NE; ++e) if (p[e] > p[i0]) i0 = e;
        int i1 = -1;
        #pragma unroll
        for (int e = 0; e < NE; ++e) {
            if (e == i0) continue;
            if (i1 < 0 || p[e] > p[i1]) i1 = e;
        }
        int pos0 = atomicAdd(&g_cnt[i0], 1);
        g_tok [i0 * T_TOKENS + pos0] = t;
        g_slot[i0 * T_TOKENS + pos0] = 0;
        g_wt  [i0 * T_TOKENS + pos0] = p[i0];
        int pos1 = atomicAdd(&g_cnt[i1], 1);
        g_tok [i1 * T_TOKENS + pos1] = t;
        g_slot[i1 * T_TOKENS + pos1] = 1;
        g_wt  [i1 * T_TOKENS + pos1] = p[i1];

        g_sgate[t] = 1.f / (1.f + expf(-sred[0]));
    }
}

// ---------------------------------------------------------------------------
// fp32 -> fp16 hi/lo split (hidden only: 8MB, ~4us)
// ---------------------------------------------------------------------------
__global__ __launch_bounds__(256) void split_kernel(
    const float* __restrict__ src, __half* __restrict__ hi, __half* __restrict__ lo, int n4)
{
    for (int i = blockIdx.x * 256 + threadIdx.x; i < n4; i += gridDim.x * 256) {
        float4 v = ((const float4*)src)[i];
        __half hx = __float2half_rn(v.x);
        __half hy = __float2half_rn(v.y);
        __half hz = __float2half_rn(v.z);
        __half hw = __float2half_rn(v.w);
        __half lx = __float2half_rn(v.x - __half2float(hx));
        __half ly = __float2half_rn(v.y - __half2float(hy));
        __half lz = __float2half_rn(v.z - __half2float(hz));
        __half lw = __float2half_rn(v.w - __half2float(hw));
        ((__half2*)hi)[2 * i]     = __halves2half2(hx, hy);
        ((__half2*)hi)[2 * i + 1] = __halves2half2(hz, hw);
        ((__half2*)lo)[2 * i]     = __halves2half2(lx, ly);
        ((__half2*)lo)[2 * i + 1] = __halves2half2(lz, lw);
    }
}

// ---------------------------------------------------------------------------
// helpers
// ---------------------------------------------------------------------------
__device__ __forceinline__ uint32_t smem_u32(const void* p) {
    return (uint32_t)__cvta_generic_to_shared(p);
}
__device__ __forceinline__ void ldsm_x4(uint32_t* r, uint32_t a) {
    asm volatile("ldmatrix.sync.aligned.m8n8.x4.shared.b16 {%0,%1,%2,%3}, [%4];"
                 : "=r"(r[0]), "=r"(r[1]), "=r"(r[2]), "=r"(r[3]) : "r"(a));
}
__device__ __forceinline__ void ldsm_x4_t(uint32_t* r, uint32_t a) {
    asm volatile("ldmatrix.sync.aligned.m8n8.x4.trans.shared.b16 {%0,%1,%2,%3}, [%4];"
                 : "=r"(r[0]), "=r"(r[1]), "=r"(r[2]), "=r"(r[3]) : "r"(a));
}
__device__ __forceinline__ void mma16816(float* d, const uint32_t* a, uint32_t b0, uint32_t b1) {
    asm("mma.sync.aligned.m16n8k16.row.col.f32.f16.f16.f32 "
        "{%0,%1,%2,%3}, {%4,%5,%6,%7}, {%8,%9}, {%0,%1,%2,%3};"
        : "+f"(d[0]), "+f"(d[1]), "+f"(d[2]), "+f"(d[3])
        : "r"(a[0]), "r"(a[1]), "r"(a[2]), "r"(a[3]), "r"(b0), "r"(b1));
}
__device__ __forceinline__ uint32_t h2bits(__half2 h) {
    return *reinterpret_cast<uint32_t*>(&h);
}
__device__ __forceinline__ void split2h(float a, float b, uint32_t& hi, uint32_t& lo) {
    __half ha = __float2half_rn(a), hb = __float2half_rn(b);
    hi = h2bits(__halves2half2(ha, hb));
    lo = h2bits(__halves2half2(__float2half_rn(a - __half2float(ha)),
                               __float2half_rn(b - __half2float(hb))));
}

#define CP16(dst, src) \
    asm volatile("cp.async.cg.shared.global [%0], [%1], 16;" :: "r"(dst), "l"(src) : "memory")
#define CP_COMMIT() asm volatile("cp.async.commit_group;" ::: "memory")
#define CP_WAIT(n)  asm volatile("cp.async.wait_group %0;" :: "n"(n) : "memory")

#define ASTRIDE 80
#define ALO_OFF 10240

// ---------------------------------------------------------------------------
// FUSED gate+up GEMM for expert AND shared paths in one launch (wave packing).
// blockIdx.x < 704: shared-expert tile (Ntot=SI, full tokens).
// else: expert tile (Ntot=I, gathered rows, per-expert weights).
// TILE_N=128 = [gate 64 | up 64]; epilogue silu(g)*u -> fp16 hi/lo.
// ---------------------------------------------------------------------------
#define GU_SH_BLOCKS (SI_DIM / 64 * (T_TOKENS / 128))            // 88*8 = 704
#define GU_EXP_BLOCKS (I_DIM / 64 * (T_TOKENS / 128) * NE)       // 22*8*8 = 1408

__global__ void __launch_bounds__(256, 2) gateup_fused(
    const __half* __restrict__ Ahi, const __half* __restrict__ Alo,
    const float* __restrict__ wg, const float* __restrict__ wu,
    const float* __restrict__ swg, const float* __restrict__ swu,
    __half* __restrict__ actHi, __half* __restrict__ actLo,
    __half* __restrict__ shHi, __half* __restrict__ shLo)
{
    constexpr int NW = 64, NJ = 8, CPT = 16, NF4 = 4;
    constexpr int BSTR = 272, BSZ = 32 * BSTR;        // 8704
    constexpr int BHI = 20480, STG = 20480 + BSZ;     // 29184
    constexpr int K = H_DIM;

    int isExp, e, m0, n0, Ntot;
    const float *B0, *B1;
    __half *oHi, *oLo;
    {
        const int bid = blockIdx.x;
        if (bid < GU_SH_BLOCKS) {
            isExp = 0; e = 0;
            m0 = (bid / (SI_DIM / 64)) * 128;
            n0 = (bid % (SI_DIM / 64)) * 64;
            Ntot = SI_DIM; B0 = swg; B1 = swu; oHi = shHi; oLo = shLo;
        } else {
            const int t = bid - GU_SH_BLOCKS;
            const int per_e = (I_DIM / 64) * (T_TOKENS / 128);   // 176
            isExp = 1; e = t / per_e;
            const int rem = t % per_e;
            m0 = (rem / (I_DIM / 64)) * 128;
            n0 = (rem % (I_DIM / 64)) * 64;
            Ntot = I_DIM; B0 = wg; B1 = wu; oHi = actHi; oLo = actLo;
        }
    }
    const int cnt = isExp ? g_cnt[e] : T_TOKENS;
    if (m0 >= cnt) return;

    extern __shared__ char db[];
    __shared__ int s_tok[128];

    const int tid  = threadIdx.x;
    const int lane = tid & 31;
    const int warp = tid >> 5;
    const int wm = warp & 3;
    const int wn = warp >> 2;

    if (isExp && tid < 128) {
        int gm = m0 + tid;
        s_tok[tid] = (gm < cnt) ? g_tok[e * T_TOKENS + gm] : 0;
    }
    __syncthreads();

    // ---- A loader ----
    const int arow_l = tid >> 1;
    size_t arow = isExp ? (size_t)s_tok[arow_l] : (size_t)(m0 + arow_l);
    const __half* aHiP = Ahi + arow * K + (tid & 1) * 16;
    const __half* aLoP = Alo + arow * K + (tid & 1) * 16;
    const uint32_t aDst = smem_u32(db) + (uint32_t)(arow_l * ASTRIDE + (tid & 1) * 32);

    auto issueA = [&](int k0, int s) {
        const uint32_t so = (uint32_t)(s * STG);
        CP16(aDst + so,      aHiP + k0);
        CP16(aDst + so + 16, aHiP + k0 + 8);
        CP16(aDst + so + ALO_OFF,      aLoP + k0);
        CP16(aDst + so + ALO_OFF + 16, aLoP + k0 + 8);
    };

    // ---- B loader ----
    const int bkr = tid >> 3;
    const int seg = (tid & 7) * CPT;
    const size_t eoff = isExp ? (size_t)e * K * Ntot : 0;
    const float* BP = (seg < NW ? B0 + eoff + n0 + seg : B1 + eoff + n0 + seg - NW)
                      + (size_t)bkr * Ntot;
    const uint32_t bOff = (uint32_t)(bkr * BSTR + seg * 2);

    float4 pb[NF4];
    auto ldgB = [&](int k0) {
        const float4* p = (const float4*)(BP + (size_t)k0 * Ntot);
        #pragma unroll
        for (int i = 0; i < NF4; ++i) pb[i] = p[i];
    };
    auto stsB = [&](int s) {
        char* st = db + s * STG;
        #pragma unroll
        for (int i = 0; i < NF4 / 2; ++i) {
            const uint32_t u0 = h2bits(__floats2half2_rn(pb[2 * i].x,     pb[2 * i].y));
            const uint32_t u1 = h2bits(__floats2half2_rn(pb[2 * i].z,     pb[2 * i].w));
            const uint32_t u2 = h2bits(__floats2half2_rn(pb[2 * i + 1].x, pb[2 * i + 1].y));
            const uint32_t u3 = h2bits(__floats2half2_rn(pb[2 * i + 1].z, pb[2 * i + 1].w));
            *(uint4*)(st + BHI + bOff + i * 16) = make_uint4(u0, u1, u2, u3);
        }
    };

    float acc[2][NJ][4];
    #pragma unroll
    for (int i = 0; i < 2; ++i)
        #pragma unroll
        for (int j = 0; j < NJ; ++j)
            #pragma unroll
            for (int v = 0; v < 4; ++v) acc[i][j][v] = 0.f;

    const int grp = lane >> 3;
    const int gl  = lane & 7;
    const int a_row_off = (grp & 1) * 8 + gl;
    const int a_col_off = (grp >> 1) * 8;
    const int b_row_off = (grp & 1) * 8 + gl;
    const int b_col_off = (grp >> 1) * 8;

    const int C = K / 32;
    ldgB(0);
    issueA(0, 0);
    CP_COMMIT();

    for (int c = 0; c < C; ++c) {
        if (c + 1 < C) {
            issueA((c + 1) * 32, (c + 1) & 1);
            CP_COMMIT();
            CP_WAIT(1);
        } else {
            CP_WAIT(0);
        }
        stsB(c & 1);
        if (c + 1 < C) ldgB((c + 1) * 32);
        __syncthreads();

        const uint32_t base = smem_u32(db) + (uint32_t)((c & 1) * STG);
        #pragma unroll
        for (int ks = 0; ks < 32; ks += 16) {
            uint32_t ah[2][4], al[2][4];
            #pragma unroll
            for (int mi = 0; mi < 2; ++mi) {
                const uint32_t ra = base + (uint32_t)((wm * 32 + mi * 16 + a_row_off) * ASTRIDE + (ks + a_col_off) * 2);
                ldsm_x4(ah[mi], ra);
                ldsm_x4(al[mi], ra + ALO_OFF);
            }
            #pragma unroll
            for (int g = 0; g < NW / 16; ++g) {
                uint32_t bh[4];
                const uint32_t rb = base + (uint32_t)(BHI + (ks + b_row_off) * BSTR + (wn * NW + g * 16 + b_col_off) * 2);
                ldsm_x4_t(bh, rb);
                #pragma unroll
                for (int mi = 0; mi < 2; ++mi)
                    #pragma unroll
                    for (int half = 0; half < 2; ++half)
                        mma16816(acc[mi][g * 2 + half], ah[mi], bh[half * 2], bh[half * 2 + 1]);
                #pragma unroll
                for (int mi = 0; mi < 2; ++mi)
                    #pragma unroll
                    for (int half = 0; half < 2; ++half)
                        mma16816(acc[mi][g * 2 + half], al[mi], bh[half * 2], bh[half * 2 + 1]);
            }
        }
        __syncthreads();
    }

    // ---- epilogue: silu(g)*u -> fp16 hi/lo ----
    constexpr int EXS = NW + 8;
    float* exch = (float*)db;
    if (wn == 1) {
        #pragma unroll
        for (int mi = 0; mi < 2; ++mi)
            #pragma unroll
            for (int nj = 0; nj < NJ; ++nj) {
                const int cl = nj * 8 + (lane & 3) * 2;
                #pragma unroll
                for (int h = 0; h < 2; ++h) {
                    const int rl = wm * 32 + mi * 16 + (lane >> 2) + h * 8;
                    exch[rl * EXS + cl]     = acc[mi][nj][h * 2];
                    exch[rl * EXS + cl + 1] = acc[mi][nj][h * 2 + 1];
                }
            }
    }
    __syncthreads();
    if (wn == 0) {
        #pragma unroll
        for (int mi = 0; mi < 2; ++mi)
            #pragma unroll
            for (int h = 0; h < 2; ++h) {
                const int rl = wm * 32 + mi * 16 + (lane >> 2) + h * 8;
                const int r = m0 + rl;
                if (isExp && r >= cnt) continue;
                const size_t row = (isExp ? (size_t)e * T_TOKENS : 0) + r;
                #pragma unroll
                for (int nj = 0; nj < NJ; ++nj) {
                    const int cl = nj * 8 + (lane & 3) * 2;
                    const float g0 = acc[mi][nj][h * 2];
                    const float g1 = acc[mi][nj][h * 2 + 1];
                    const float u0 = exch[rl * EXS + cl];
                    const float u1 = exch[rl * EXS + cl + 1];
                    const float a0 = (g0 / (1.f + expf(-g0))) * u0;
                    const float a1 = (g1 / (1.f + expf(-g1))) * u1;
                    uint32_t hi, lo; split2h(a0, a1, hi, lo);
                    *(uint32_t*)(oHi + row * Ntot + n0 + cl) = hi;
                    *(uint32_t*)(oLo + row * Ntot + n0 + cl) = lo;
                }
            }
    }
}

// ---------------------------------------------------------------------------
// Down GEMM (fp16 2-term). EPI=1: expert scatter x weight.
// EPI=2: shared combine (sigmoid gate + contrib -> outF).
// ---------------------------------------------------------------------------
template<int AEXP, int EPI, int TILE_N>
__global__ void __launch_bounds__(256, 2) down_gemm(
    const __half* __restrict__ Ahi, const __half* __restrict__ Alo,
    const float* __restrict__ B0,
    float* __restrict__ outF, int K, int Ntot)
{
    constexpr int NW   = TILE_N / 2;
    constexpr int NJ   = NW / 8;
    constexpr int CPT  = TILE_N / 8;
    constexpr int NF4  = CPT / 4;
    constexpr int BSTR = TILE_N * 2 + 16;
    constexpr int BSZ  = 32 * BSTR;
    constexpr int BHI  = 20480;
    constexpr int STG  = 20480 + BSZ;

    const int e  = blockIdx.z;
    const int m0 = blockIdx.y * 128;
    const int n0 = blockIdx.x * TILE_N;
    const int cnt = AEXP ? g_cnt[e] : T_TOKENS;
    if (m0 >= cnt) return;

    extern __shared__ char db[];

    const int tid  = threadIdx.x;
    const int lane = tid & 31;
    const int warp = tid >> 5;
    const int wm = warp & 3;
    const int wn = warp >> 2;

    const int arow_l = tid >> 1;
    const size_t arow = (AEXP ? (size_t)e * T_TOKENS : 0) + m0 + arow_l;
    const __half* aHiP = Ahi + arow * K + (tid & 1) * 16;
    const __half* aLoP = Alo + arow * K + (tid & 1) * 16;
    const uint32_t aDst = smem_u32(db) + (uint32_t)(arow_l * ASTRIDE + (tid & 1) * 32);

    auto issueA = [&](int k0, int s) {
        const uint32_t so = (uint32_t)(s * STG);
        CP16(aDst + so,      aHiP + k0);
        CP16(aDst + so + 16, aHiP + k0 + 8);
        CP16(aDst + so + ALO_OFF,      aLoP + k0);
        CP16(aDst + so + ALO_OFF + 16, aLoP + k0 + 8);
    };

    const int bkr = tid >> 3;
    const int seg = (tid & 7) * CPT;
    const size_t eoff = AEXP ? (size_t)e * K * Ntot : 0;
    const float* BP = B0 + eoff + n0 + seg + (size_t)bkr * Ntot;
    const uint32_t bOff = (uint32_t)(bkr * BSTR + seg * 2);

    float4 pb[NF4];
    auto ldgB = [&](int k0) {
        const float4* p = (const float4*)(BP + (size_t)k0 * Ntot);
        #pragma unroll
        for (int i = 0; i < NF4; ++i) pb[i] = p[i];
    };
    auto stsB = [&](int s) {
        char* st = db + s * STG;
        #pragma unroll
        for (int i = 0; i < NF4 / 2; ++i) {
            const uint32_t u0 = h2bits(__floats2half2_rn(pb[2 * i].x,     pb[2 * i].y));
            const uint32_t u1 = h2bits(__floats2half2_rn(pb[2 * i].z,     pb[2 * i].w));
            const uint32_t u2 = h2bits(__floats2half2_rn(pb[2 * i + 1].x, pb[2 * i + 1].y));
            const uint32_t u3 = h2bits(__floats2half2_rn(pb[2 * i + 1].z, pb[2 * i + 1].w));
            *(uint4*)(st + BHI + bOff + i * 16) = make_uint4(u0, u1, u2, u3);
        }
    };

    float acc[2][NJ][4];
    #pragma unroll
    for (int i = 0; i < 2; ++i)
        #pragma unroll
        for (int j = 0; j < NJ; ++j)
            #pragma unroll
            for (int v = 0; v < 4; ++v) acc[i][j][v] = 0.f;

    const int grp = lane >> 3;
    const int gl  = lane & 7;
    const int a_row_off = (grp & 1) * 8 + gl;
    const int a_col_off = (grp >> 1) * 8;
    const int b_row_off = (grp & 1) * 8 + gl;
    const int b_col_off = (grp >> 1) * 8;

    const int C = K / 32;
    ldgB(0);
    issueA(0, 0);
    CP_COMMIT();

    for (int c = 0; c < C; ++c) {
        if (c + 1 < C) {
            issueA((c + 1) * 32, (c + 1) & 1);
            CP_COMMIT();
            CP_WAIT(1);
        } else {
            CP_WAIT(0);
        }
        stsB(c & 1);
        if (c + 1 < C) ldgB((c + 1) * 32);
        __syncthreads();

        const uint32_t base = smem_u32(db) + (uint32_t)((c & 1) * STG);
        #pragma unroll
        for (int ks = 0; ks < 32; ks += 16) {
            uint32_t ah[2][4], al[2][4];
            #pragma unroll
            for (int mi = 0; mi < 2; ++mi) {
                const uint32_t ra = base + (uint32_t)((wm * 32 + mi * 16 + a_row_off) * ASTRIDE + (ks + a_col_off) * 2);
                ldsm_x4(ah[mi], ra);
                ldsm_x4(al[mi], ra + ALO_OFF);
            }
            #pragma unroll
            for (int g = 0; g < NW / 16; ++g) {
                uint32_t bh[4];
                const uint32_t rb = base + (uint32_t)(BHI + (ks + b_row_off) * BSTR + (wn * NW + g * 16 + b_col_off) * 2);
                ldsm_x4_t(bh, rb);
                #pragma unroll
                for (int mi = 0; mi < 2; ++mi)
                    #pragma unroll
                    for (int half = 0; half < 2; ++half)
                        mma16816(acc[mi][g * 2 + half], ah[mi], bh[half * 2], bh[half * 2 + 1]);
                #pragma unroll
                for (int mi = 0; mi < 2; ++mi)
                    #pragma unroll
                    for (int half = 0; half < 2; ++half)
                        mma16816(acc[mi][g * 2 + half], al[mi], bh[half * 2], bh[half * 2 + 1]);
            }
        }
        __syncthreads();
    }

    #pragma unroll
    for (int mi = 0; mi < 2; ++mi)
        #pragma unroll
        for (int h = 0; h < 2; ++h) {
            const int rl = wm * 32 + mi * 16 + (lane >> 2) + h * 8;
            const int r = m0 + rl;
            if (EPI == 1) {
                if (r >= cnt) continue;
                const int idx = e * T_TOKENS + r;
                const float w = g_wt[idx];
                float* orow = g_contrib + ((size_t)g_tok[idx] * 2 + g_slot[idx]) * H_DIM;
                #pragma unroll
                for (int nj = 0; nj < NJ; ++nj) {
                    const int c = n0 + wn * NW + nj * 8 + (lane & 3) * 2;
                    float2 o = {acc[mi][nj][h * 2] * w, acc[mi][nj][h * 2 + 1] * w};
                    *(float2*)(orow + c) = o;
                }
            } else {
                const float sg = g_sgate[r];
                #pragma unroll
                for (int nj = 0; nj < NJ; ++nj) {
                    const int c = n0 + wn * NW + nj * 8 + (lane & 3) * 2;
                    const float2 c0 = *(const float2*)(g_contrib + ((size_t)r * 2 + 0) * H_DIM + c);
                    const float2 c1 = *(const float2*)(g_contrib + ((size_t)r * 2 + 1) * H_DIM + c);
                    float2 o = {sg * acc[mi][nj][h * 2] + c0.x + c1.x,
                                sg * acc[mi][nj][h * 2 + 1] + c0.y + c1.y};
                    *(float2*)(outF + (size_t)r * H_DIM + c) = o;
                }
            }
        }
}

// ---------------------------------------------------------------------------
extern "C" void kernel_launch(void* const* d_in, const int* in_sizes, int n_in,
                              void* d_out, int out_size)
{
    const float* hidden        = (const float*)d_in[0];
    const float* gate_w        = (const float*)d_in[1];
    const float* w_gate        = (const float*)d_in[2];
    const float* w_up          = (const float*)d_in[3];
    const float* w_down        = (const float*)d_in[4];
    const float* sw_gate       = (const float*)d_in[5];
    const float* sw_up         = (const float*)d_in[6];
    const float* sw_down       = (const float*)d_in[7];
    const float* shared_gate_w = (const float*)d_in[8];

    float* out        = (float*)d_out;
    float* out_logits = out + (size_t)T_TOKENS * H_DIM;

    __half *hidHi, *hidLo, *actHi, *actLo, *shHi, *shLo;
    cudaGetSymbolAddress((void**)&hidHi, g_hid_hi);  cudaGetSymbolAddress((void**)&hidLo, g_hid_lo);
    cudaGetSymbolAddress((void**)&actHi, g_act_hi);  cudaGetSymbolAddress((void**)&actLo, g_act_lo);
    cudaGetSymbolAddress((void**)&shHi, g_shact_hi); cudaGetSymbolAddress((void**)&shLo, g_shact_lo);

    const int SM128 = 2 * (20480 + 32 * (128 * 2 + 16));  // 58368
    const int SM64  = 2 * (20480 + 32 * (64 * 2 + 16));   // 50176

    cudaFuncSetAttribute(gateup_fused,        cudaFuncAttributeMaxDynamicSharedMemorySize, SM128);
    cudaFuncSetAttribute(down_gemm<1,1,128>,  cudaFuncAttributeMaxDynamicSharedMemorySize, SM128);
    cudaFuncSetAttribute(down_gemm<0,2,64>,   cudaFuncAttributeMaxDynamicSharedMemorySize, SM64);

    zero_cnt_kernel<<<1, 32>>>();
    router_kernel<<<T_TOKENS, 256>>>(hidden, gate_w, shared_gate_w, out_logits);

    // hidden split only (8MB, ~4us)
    {
        int n4 = (int)((size_t)T_TOKENS * H_DIM / 4);
        split_kernel<<<(n4 + 255) / 256, 256>>>(hidden, hidHi, hidLo, n4);
    }

    // fused expert+shared gate/up (wave-packed single launch)
    gateup_fused<<<GU_SH_BLOCKS + GU_EXP_BLOCKS, 256, SM128>>>(
        hidHi, hidLo, w_gate, w_up, sw_gate, sw_up, actHi, actLo, shHi, shLo);

    // expert down -> contrib scatter
    down_gemm<1,1,128><<<dim3(H_DIM / 128, T_TOKENS / 128, NE), 256, SM128>>>(
        actHi, actLo, w_down, nullptr, I_DIM, H_DIM);

    // shared down + combine -> out (64-wide tiles: 256 CTAs, better last-wave parallelism)
    down_gemm<0,2,64><<<dim3(H_DIM / 64, T_TOKENS / 128, 1), 256, SM64>>>(
        shHi, shLo, sw_down, out, SI_DIM, H_DIM);
}

// round 15
// speedup vs baseline: 2.0092x; 1.4443x over previous
#include <cuda_runtime.h>
#include <cuda_fp16.h>
#include <math.h>
#include <stdint.h>

#define T_TOKENS 1024
#define H_DIM    2048
#define I_DIM    1408
#define SI_DIM   5632
#define NE       8

// ---------------------------------------------------------------------------
// Scratch (__device__ globals; no cudaMalloc allowed)
// ---------------------------------------------------------------------------
__device__ int   g_cnt[NE];
__device__ int   g_tok [NE * T_TOKENS];
__device__ int   g_slot[NE * T_TOKENS];
__device__ float g_wt  [NE * T_TOKENS];
__device__ float g_sgate[T_TOKENS];

__device__ __half g_hid[(size_t)T_TOKENS * H_DIM];
__device__ __half g_act[(size_t)NE * T_TOKENS * I_DIM];
__device__ __half g_shact[(size_t)T_TOKENS * SI_DIM];
__device__ float  g_contrib[(size_t)T_TOKENS * 2 * H_DIM];

// ---------------------------------------------------------------------------
__global__ void zero_cnt_kernel() {
    if (threadIdx.x < NE) g_cnt[threadIdx.x] = 0;
}

__global__ __launch_bounds__(256) void router_kernel(
    const float* __restrict__ hidden,
    const float* __restrict__ gate_w,
    const float* __restrict__ shared_gate_w,
    float* __restrict__ out_logits)
{
    const int t = blockIdx.x;
    __shared__ float sh[H_DIM];
    __shared__ float slog[NE];
    __shared__ float sred[256];

    const float* hrow = hidden + (size_t)t * H_DIM;
    for (int i = threadIdx.x; i < H_DIM; i += 256) sh[i] = hrow[i];
    __syncthreads();

    const int warp = threadIdx.x >> 5;
    const int lane = threadIdx.x & 31;

    float sum = 0.f;
    for (int k = lane; k < H_DIM; k += 32) sum += sh[k] * gate_w[k * NE + warp];
    #pragma unroll
    for (int o = 16; o; o >>= 1) sum += __shfl_down_sync(0xffffffffu, sum, o);
    if (lane == 0) slog[warp] = sum;

    float s2 = 0.f;
    for (int k = threadIdx.x; k < H_DIM; k += 256) s2 += sh[k] * shared_gate_w[k];
    sred[threadIdx.x] = s2;
    __syncthreads();
    for (int st = 128; st; st >>= 1) {
        if (threadIdx.x < st) sred[threadIdx.x] += sred[threadIdx.x + st];
        __syncthreads();
    }

    if (threadIdx.x == 0) {
        float lg[NE];
        float mx = -1e30f;
        #pragma unroll
        for (int e = 0; e < NE; ++e) { lg[e] = slog[e]; mx = fmaxf(mx, lg[e]); }
        float p[NE]; float den = 0.f;
        #pragma unroll
        for (int e = 0; e < NE; ++e) { p[e] = expf(lg[e] - mx); den += p[e]; }
        float inv = 1.f / den;
        #pragma unroll
        for (int e = 0; e < NE; ++e) {
            p[e] *= inv;
            out_logits[(size_t)t * NE + e] = lg[e];
        }
        int i0 = 0;
        #pragma unroll
        for (int e = 1; e < NE; ++e) if (p[e] > p[i0]) i0 = e;
        int i1 = -1;
        #pragma unroll
        for (int e = 0; e < NE; ++e) {
            if (e == i0) continue;
            if (i1 < 0 || p[e] > p[i1]) i1 = e;
        }
        int pos0 = atomicAdd(&g_cnt[i0], 1);
        g_tok [i0 * T_TOKENS + pos0] = t;
        g_slot[i0 * T_TOKENS + pos0] = 0;
        g_wt  [i0 * T_TOKENS + pos0] = p[i0];
        int pos1 = atomicAdd(&g_cnt[i1], 1);
        g_tok [i1 * T_TOKENS + pos1] = t;
        g_slot[i1 * T_TOKENS + pos1] = 1;
        g_wt  [i1 * T_TOKENS + pos1] = p[i1];

        g_sgate[t] = 1.f / (1.f + expf(-sred[0]));
    }
}

// ---------------------------------------------------------------------------
// fp32 -> fp16 convert (hidden only: 8MB, ~3us)
// ---------------------------------------------------------------------------
__global__ __launch_bounds__(256) void cvt_kernel(
    const float* __restrict__ src, __half* __restrict__ dst, int n4)
{
    for (int i = blockIdx.x * 256 + threadIdx.x; i < n4; i += gridDim.x * 256) {
        float4 v = ((const float4*)src)[i];
        ((__half2*)dst)[2 * i]     = __floats2half2_rn(v.x, v.y);
        ((__half2*)dst)[2 * i + 1] = __floats2half2_rn(v.z, v.w);
    }
}

// ---------------------------------------------------------------------------
// helpers
// ---------------------------------------------------------------------------
__device__ __forceinline__ uint32_t smem_u32(const void* p) {
    return (uint32_t)__cvta_generic_to_shared(p);
}
__device__ __forceinline__ void ldsm_x4(uint32_t* r, uint32_t a) {
    asm volatile("ldmatrix.sync.aligned.m8n8.x4.shared.b16 {%0,%1,%2,%3}, [%4];"
                 : "=r"(r[0]), "=r"(r[1]), "=r"(r[2]), "=r"(r[3]) : "r"(a));
}
__device__ __forceinline__ void ldsm_x4_t(uint32_t* r, uint32_t a) {
    asm volatile("ldmatrix.sync.aligned.m8n8.x4.trans.shared.b16 {%0,%1,%2,%3}, [%4];"
                 : "=r"(r[0]), "=r"(r[1]), "=r"(r[2]), "=r"(r[3]) : "r"(a));
}
__device__ __forceinline__ void mma16816(float* d, const uint32_t* a, uint32_t b0, uint32_t b1) {
    asm("mma.sync.aligned.m16n8k16.row.col.f32.f16.f16.f32 "
        "{%0,%1,%2,%3}, {%4,%5,%6,%7}, {%8,%9}, {%0,%1,%2,%3};"
        : "+f"(d[0]), "+f"(d[1]), "+f"(d[2]), "+f"(d[3])
        : "r"(a[0]), "r"(a[1]), "r"(a[2]), "r"(a[3]), "r"(b0), "r"(b1));
}
__device__ __forceinline__ uint32_t h2bits(__half2 h) {
    return *reinterpret_cast<uint32_t*>(&h);
}

#define CP16(dst, src) \
    asm volatile("cp.async.cg.shared.global [%0], [%1], 16;" :: "r"(dst), "l"(src) : "memory")
#define CP_COMMIT() asm volatile("cp.async.commit_group;" ::: "memory")
#define CP_WAIT(n)  asm volatile("cp.async.wait_group %0;" :: "n"(n) : "memory")

#define ASTRIDE 80
#define A_BYTES 10240

// ---------------------------------------------------------------------------
// FUSED gate+up GEMM (pure fp16, fp32 accum) for expert AND shared paths.
// blockIdx.x < 704: shared tile; else expert tile (gathered rows).
// TILE_N=128 = [gate 64 | up 64]; epilogue silu(g)*u -> fp16.
// ---------------------------------------------------------------------------
#define GU_SH_BLOCKS (SI_DIM / 64 * (T_TOKENS / 128))            // 704
#define GU_EXP_BLOCKS (I_DIM / 64 * (T_TOKENS / 128) * NE)       // 1408

__global__ void __launch_bounds__(256, 2) gateup_fused(
    const __half* __restrict__ A,
    const float* __restrict__ wg, const float* __restrict__ wu,
    const float* __restrict__ swg, const float* __restrict__ swu,
    __half* __restrict__ actO, __half* __restrict__ shO)
{
    constexpr int NW = 64, NJ = 8, CPT = 16, NF4 = 4;
    constexpr int BSTR = 272, BSZ = 32 * BSTR;      // 8704
    constexpr int STG = A_BYTES + BSZ;              // 18944
    constexpr int K = H_DIM;

    int isExp, e, m0, n0, Ntot;
    const float *B0, *B1;
    __half *oP;
    {
        const int bid = blockIdx.x;
        if (bid < GU_SH_BLOCKS) {
            isExp = 0; e = 0;
            m0 = (bid / (SI_DIM / 64)) * 128;
            n0 = (bid % (SI_DIM / 64)) * 64;
            Ntot = SI_DIM; B0 = swg; B1 = swu; oP = shO;
        } else {
            const int t = bid - GU_SH_BLOCKS;
            const int per_e = (I_DIM / 64) * (T_TOKENS / 128);   // 176
            isExp = 1; e = t / per_e;
            const int rem = t % per_e;
            m0 = (rem / (I_DIM / 64)) * 128;
            n0 = (rem % (I_DIM / 64)) * 64;
            Ntot = I_DIM; B0 = wg; B1 = wu; oP = actO;
        }
    }
    const int cnt = isExp ? g_cnt[e] : T_TOKENS;
    if (m0 >= cnt) return;

    extern __shared__ char db[];
    __shared__ int s_tok[128];

    const int tid  = threadIdx.x;
    const int lane = tid & 31;
    const int warp = tid >> 5;
    const int wm = warp & 3;
    const int wn = warp >> 2;

    if (isExp && tid < 128) {
        int gm = m0 + tid;
        s_tok[tid] = (gm < cnt) ? g_tok[e * T_TOKENS + gm] : 0;
    }
    __syncthreads();

    // ---- A loader (fp16): thread -> row tid>>1, 16 k elems at (tid&1)*16 ----
    const int arow_l = tid >> 1;
    size_t arow = isExp ? (size_t)s_tok[arow_l] : (size_t)(m0 + arow_l);
    const __half* aP = A + arow * K + (tid & 1) * 16;
    const uint32_t aDst = smem_u32(db) + (uint32_t)(arow_l * ASTRIDE + (tid & 1) * 32);

    auto issueA = [&](int k0, int s) {
        const uint32_t so = (uint32_t)(s * STG);
        CP16(aDst + so,      aP + k0);
        CP16(aDst + so + 16, aP + k0 + 8);
    };

    // ---- B loader (fp32 LDG -> fp16 regs -> smem) ----
    const int bkr = tid >> 3;
    const int seg = (tid & 7) * CPT;
    const size_t eoff = isExp ? (size_t)e * K * Ntot : 0;
    const float* BP = (seg < NW ? B0 + eoff + n0 + seg : B1 + eoff + n0 + seg - NW)
                      + (size_t)bkr * Ntot;
    const uint32_t bOff = (uint32_t)(bkr * BSTR + seg * 2);

    float4 pb[NF4];
    auto ldgB = [&](int k0) {
        const float4* p = (const float4*)(BP + (size_t)k0 * Ntot);
        #pragma unroll
        for (int i = 0; i < NF4; ++i) pb[i] = p[i];
    };
    auto stsB = [&](int s) {
        char* st = db + s * STG + A_BYTES;
        #pragma unroll
        for (int i = 0; i < NF4 / 2; ++i) {
            const uint32_t u0 = h2bits(__floats2half2_rn(pb[2 * i].x,     pb[2 * i].y));
            const uint32_t u1 = h2bits(__floats2half2_rn(pb[2 * i].z,     pb[2 * i].w));
            const uint32_t u2 = h2bits(__floats2half2_rn(pb[2 * i + 1].x, pb[2 * i + 1].y));
            const uint32_t u3 = h2bits(__floats2half2_rn(pb[2 * i + 1].z, pb[2 * i + 1].w));
            *(uint4*)(st + bOff + i * 16) = make_uint4(u0, u1, u2, u3);
        }
    };

    float acc[2][NJ][4];
    #pragma unroll
    for (int i = 0; i < 2; ++i)
        #pragma unroll
        for (int j = 0; j < NJ; ++j)
            #pragma unroll
            for (int v = 0; v < 4; ++v) acc[i][j][v] = 0.f;

    const int grp = lane >> 3;
    const int gl  = lane & 7;
    const int a_row_off = (grp & 1) * 8 + gl;
    const int a_col_off = (grp >> 1) * 8;
    const int b_row_off = (grp & 1) * 8 + gl;
    const int b_col_off = (grp >> 1) * 8;

    const int C = K / 32;
    ldgB(0);
    issueA(0, 0);
    CP_COMMIT();

    for (int c = 0; c < C; ++c) {
        if (c + 1 < C) {
            issueA((c + 1) * 32, (c + 1) & 1);
            CP_COMMIT();
            CP_WAIT(1);
        } else {
            CP_WAIT(0);
        }
        stsB(c & 1);
        if (c + 1 < C) ldgB((c + 1) * 32);
        __syncthreads();

        const uint32_t base = smem_u32(db) + (uint32_t)((c & 1) * STG);
        #pragma unroll
        for (int ks = 0; ks < 32; ks += 16) {
            uint32_t ah[2][4];
            #pragma unroll
            for (int mi = 0; mi < 2; ++mi) {
                const uint32_t ra = base + (uint32_t)((wm * 32 + mi * 16 + a_row_off) * ASTRIDE + (ks + a_col_off) * 2);
                ldsm_x4(ah[mi], ra);
            }
            #pragma unroll
            for (int g = 0; g < NW / 16; ++g) {
                uint32_t bh[4];
                const uint32_t rb = base + (uint32_t)(A_BYTES + (ks + b_row_off) * BSTR + (wn * NW + g * 16 + b_col_off) * 2);
                ldsm_x4_t(bh, rb);
                #pragma unroll
                for (int mi = 0; mi < 2; ++mi)
                    #pragma unroll
                    for (int half = 0; half < 2; ++half)
                        mma16816(acc[mi][g * 2 + half], ah[mi], bh[half * 2], bh[half * 2 + 1]);
            }
        }
        __syncthreads();
    }

    // ---- epilogue: silu(g)*u -> fp16 ----
    constexpr int EXS = NW + 8;
    float* exch = (float*)db;
    if (wn == 1) {
        #pragma unroll
        for (int mi = 0; mi < 2; ++mi)
            #pragma unroll
            for (int nj = 0; nj < NJ; ++nj) {
                const int cl = nj * 8 + (lane & 3) * 2;
                #pragma unroll
                for (int h = 0; h < 2; ++h) {
                    const int rl = wm * 32 + mi * 16 + (lane >> 2) + h * 8;
                    exch[rl * EXS + cl]     = acc[mi][nj][h * 2];
                    exch[rl * EXS + cl + 1] = acc[mi][nj][h * 2 + 1];
                }
            }
    }
    __syncthreads();
    if (wn == 0) {
        #pragma unroll
        for (int mi = 0; mi < 2; ++mi)
            #pragma unroll
            for (int h = 0; h < 2; ++h) {
                const int rl = wm * 32 + mi * 16 + (lane >> 2) + h * 8;
                const int r = m0 + rl;
                if (isExp && r >= cnt) continue;
                const size_t row = (isExp ? (size_t)e * T_TOKENS : 0) + r;
                #pragma unroll
                for (int nj = 0; nj < NJ; ++nj) {
                    const int cl = nj * 8 + (lane & 3) * 2;
                    const float g0 = acc[mi][nj][h * 2];
                    const float g1 = acc[mi][nj][h * 2 + 1];
                    const float u0 = exch[rl * EXS + cl];
                    const float u1 = exch[rl * EXS + cl + 1];
                    const float a0 = (g0 / (1.f + expf(-g0))) * u0;
                    const float a1 = (g1 / (1.f + expf(-g1))) * u1;
                    *(uint32_t*)(oP + row * Ntot + n0 + cl) = h2bits(__floats2half2_rn(a0, a1));
                }
            }
    }
}

// ---------------------------------------------------------------------------
// Down GEMM (pure fp16, fp32 accum). EPI=1: expert scatter x weight.
// EPI=2: shared combine (sigmoid gate + contrib -> outF).
// ---------------------------------------------------------------------------
template<int AEXP, int EPI, int TILE_N>
__global__ void __launch_bounds__(256, 2) down_gemm(
    const __half* __restrict__ A,
    const float* __restrict__ B0,
    float* __restrict__ outF, int K, int Ntot)
{
    constexpr int NW   = TILE_N / 2;
    constexpr int NJ   = NW / 8;
    constexpr int CPT  = TILE_N / 8;
    constexpr int NF4  = CPT / 4;
    constexpr int BSTR = TILE_N * 2 + 16;
    constexpr int BSZ  = 32 * BSTR;
    constexpr int STG  = A_BYTES + BSZ;

    const int e  = blockIdx.z;
    const int m0 = blockIdx.y * 128;
    const int n0 = blockIdx.x * TILE_N;
    const int cnt = AEXP ? g_cnt[e] : T_TOKENS;
    if (m0 >= cnt) return;

    extern __shared__ char db[];

    const int tid  = threadIdx.x;
    const int lane = tid & 31;
    const int warp = tid >> 5;
    const int wm = warp & 3;
    const int wn = warp >> 2;

    const int arow_l = tid >> 1;
    const size_t arow = (AEXP ? (size_t)e * T_TOKENS : 0) + m0 + arow_l;
    const __half* aP = A + arow * K + (tid & 1) * 16;
    const uint32_t aDst = smem_u32(db) + (uint32_t)(arow_l * ASTRIDE + (tid & 1) * 32);

    auto issueA = [&](int k0, int s) {
        const uint32_t so = (uint32_t)(s * STG);
        CP16(aDst + so,      aP + k0);
        CP16(aDst + so + 16, aP + k0 + 8);
    };

    const int bkr = tid >> 3;
    const int seg = (tid & 7) * CPT;
    const size_t eoff = AEXP ? (size_t)e * K * Ntot : 0;
    const float* BP = B0 + eoff + n0 + seg + (size_t)bkr * Ntot;
    const uint32_t bOff = (uint32_t)(bkr * BSTR + seg * 2);

    float4 pb[NF4];
    auto ldgB = [&](int k0) {
        const float4* p = (const float4*)(BP + (size_t)k0 * Ntot);
        #pragma unroll
        for (int i = 0; i < NF4; ++i) pb[i] = p[i];
    };
    auto stsB = [&](int s) {
        char* st = db + s * STG + A_BYTES;
        #pragma unroll
        for (int i = 0; i < NF4 / 2; ++i) {
            const uint32_t u0 = h2bits(__floats2half2_rn(pb[2 * i].x,     pb[2 * i].y));
            const uint32_t u1 = h2bits(__floats2half2_rn(pb[2 * i].z,     pb[2 * i].w));
            const uint32_t u2 = h2bits(__floats2half2_rn(pb[2 * i + 1].x, pb[2 * i + 1].y));
            const uint32_t u3 = h2bits(__floats2half2_rn(pb[2 * i + 1].z, pb[2 * i + 1].w));
            *(uint4*)(st + bOff + i * 16) = make_uint4(u0, u1, u2, u3);
        }
    };

    float acc[2][NJ][4];
    #pragma unroll
    for (int i = 0; i < 2; ++i)
        #pragma unroll
        for (int j = 0; j < NJ; ++j)
            #pragma unroll
            for (int v = 0; v < 4; ++v) acc[i][j][v] = 0.f;

    const int grp = lane >> 3;
    const int gl  = lane & 7;
    const int a_row_off = (grp & 1) * 8 + gl;
    const int a_col_off = (grp >> 1) * 8;
    const int b_row_off = (grp & 1) * 8 + gl;
    const int b_col_off = (grp >> 1) * 8;

    const int C = K / 32;
    ldgB(0);
    issueA(0, 0);
    CP_COMMIT();

    for (int c = 0; c < C; ++c) {
        if (c + 1 < C) {
            issueA((c + 1) * 32, (c + 1) & 1);
            CP_COMMIT();
            CP_WAIT(1);
        } else {
            CP_WAIT(0);
        }
        stsB(c & 1);
        if (c + 1 < C) ldgB((c + 1) * 32);
        __syncthreads();

        const uint32_t base = smem_u32(db) + (uint32_t)((c & 1) * STG);
        #pragma unroll
        for (int ks = 0; ks < 32; ks += 16) {
            uint32_t ah[2][4];
            #pragma unroll
            for (int mi = 0; mi < 2; ++mi) {
                const uint32_t ra = base + (uint32_t)((wm * 32 + mi * 16 + a_row_off) * ASTRIDE + (ks + a_col_off) * 2);
                ldsm_x4(ah[mi], ra);
            }
            #pragma unroll
            for (int g = 0; g < NW / 16; ++g) {
                uint32_t bh[4];
                const uint32_t rb = base + (uint32_t)(A_BYTES + (ks + b_row_off) * BSTR + (wn * NW + g * 16 + b_col_off) * 2);
                ldsm_x4_t(bh, rb);
                #pragma unroll
                for (int mi = 0; mi < 2; ++mi)
                    #pragma unroll
                    for (int half = 0; half < 2; ++half)
                        mma16816(acc[mi][g * 2 + half], ah[mi], bh[half * 2], bh[half * 2 + 1]);
            }
        }
        __syncthreads();
    }

    #pragma unroll
    for (int mi = 0; mi < 2; ++mi)
        #pragma unroll
        for (int h = 0; h < 2; ++h) {
            const int rl = wm * 32 + mi * 16 + (lane >> 2) + h * 8;
            const int r = m0 + rl;
            if (EPI == 1) {
                if (r >= cnt) continue;
                const int idx = e * T_TOKENS + r;
                const float w = g_wt[idx];
                float* orow = g_contrib + ((size_t)g_tok[idx] * 2 + g_slot[idx]) * H_DIM;
                #pragma unroll
                for (int nj = 0; nj < NJ; ++nj) {
                    const int c = n0 + wn * NW + nj * 8 + (lane & 3) * 2;
                    float2 o = {acc[mi][nj][h * 2] * w, acc[mi][nj][h * 2 + 1] * w};
                    *(float2*)(orow + c) = o;
                }
            } else {
                const float sg = g_sgate[r];
                #pragma unroll
                for (int nj = 0; nj < NJ; ++nj) {
                    const int c = n0 + wn * NW + nj * 8 + (lane & 3) * 2;
                    const float2 c0 = *(const float2*)(g_contrib + ((size_t)r * 2 + 0) * H_DIM + c);
                    const float2 c1 = *(const float2*)(g_contrib + ((size_t)r * 2 + 1) * H_DIM + c);
                    float2 o = {sg * acc[mi][nj][h * 2] + c0.x + c1.x,
                                sg * acc[mi][nj][h * 2 + 1] + c0.y + c1.y};
                    *(float2*)(outF + (size_t)r * H_DIM + c) = o;
                }
            }
        }
}

// ---------------------------------------------------------------------------
extern "C" void kernel_launch(void* const* d_in, const int* in_sizes, int n_in,
                              void* d_out, int out_size)
{
    const float* hidden        = (const float*)d_in[0];
    const float* gate_w        = (const float*)d_in[1];
    const float* w_gate        = (const float*)d_in[2];
    const float* w_up          = (const float*)d_in[3];
    const float* w_down        = (const float*)d_in[4];
    const float* sw_gate       = (const float*)d_in[5];
    const float* sw_up         = (const float*)d_in[6];
    const float* sw_down       = (const float*)d_in[7];
    const float* shared_gate_w = (const float*)d_in[8];

    float* out        = (float*)d_out;
    float* out_logits = out + (size_t)T_TOKENS * H_DIM;

    __half *hid, *act, *shact;
    cudaGetSymbolAddress((void**)&hid, g_hid);
    cudaGetSymbolAddress((void**)&act, g_act);
    cudaGetSymbolAddress((void**)&shact, g_shact);

    const int SM128 = 2 * (A_BYTES + 32 * (128 * 2 + 16));  // 37888
    const int SM64  = 2 * (A_BYTES + 32 * (64 * 2 + 16));   // 29696

    cudaFuncSetAttribute(gateup_fused,        cudaFuncAttributeMaxDynamicSharedMemorySize, SM128);
    cudaFuncSetAttribute(down_gemm<1,1,128>,  cudaFuncAttributeMaxDynamicSharedMemorySize, SM128);
    cudaFuncSetAttribute(down_gemm<0,2,64>,   cudaFuncAttributeMaxDynamicSharedMemorySize, SM64);

    zero_cnt_kernel<<<1, 32>>>();
    router_kernel<<<T_TOKENS, 256>>>(hidden, gate_w, shared_gate_w, out_logits);

    // hidden -> fp16 (8MB read, 4MB write, ~3us)
    {
        int n4 = (int)((size_t)T_TOKENS * H_DIM / 4);
        cvt_kernel<<<(n4 + 255) / 256, 256>>>(hidden, hid, n4);
    }

    // fused expert+shared gate/up (wave-packed single launch)
    gateup_fused<<<GU_SH_BLOCKS + GU_EXP_BLOCKS, 256, SM128>>>(
        hid, w_gate, w_up, sw_gate, sw_up, act, shact);

    // expert down -> contrib scatter
    down_gemm<1,1,128><<<dim3(H_DIM / 128, T_TOKENS / 128, NE), 256, SM128>>>(
        act, w_down, nullptr, I_DIM, H_DIM);

    // shared down + combine -> out
    down_gemm<0,2,64><<<dim3(H_DIM / 64, T_TOKENS / 128, 1), 256, SM64>>>(
        shact, sw_down, out, SI_DIM, H_DIM);
}

// round 16
// speedup vs baseline: 2.0133x; 1.0020x over previous
#include <cuda_runtime.h>
#include <cuda_fp16.h>
#include <math.h>
#include <stdint.h>

#define T_TOKENS 1024
#define H_DIM    2048
#define I_DIM    1408
#define SI_DIM   5632
#define NE       8

// ---------------------------------------------------------------------------
// Scratch (__device__ globals; no cudaMalloc allowed)
// ---------------------------------------------------------------------------
__device__ int   g_cnt[NE];
__device__ int   g_tok [NE * T_TOKENS];
__device__ int   g_slot[NE * T_TOKENS];
__device__ float g_wt  [NE * T_TOKENS];
__device__ float g_sgate[T_TOKENS];

__device__ __half g_hid[(size_t)T_TOKENS * H_DIM];
__device__ __half g_act[(size_t)NE * T_TOKENS * I_DIM];
__device__ __half g_shact[(size_t)T_TOKENS * SI_DIM];
__device__ float  g_contrib[(size_t)T_TOKENS * 2 * H_DIM];

// fp16 weight copies (converted once per launch)
__device__ __half g_wg16[(size_t)NE * H_DIM * I_DIM];
__device__ __half g_wu16[(size_t)NE * H_DIM * I_DIM];
__device__ __half g_wd16[(size_t)NE * I_DIM * H_DIM];
__device__ __half g_swg16[(size_t)H_DIM * SI_DIM];
__device__ __half g_swu16[(size_t)H_DIM * SI_DIM];
__device__ __half g_swd16[(size_t)SI_DIM * H_DIM];

// ---------------------------------------------------------------------------
__global__ void zero_cnt_kernel() {
    if (threadIdx.x < NE) g_cnt[threadIdx.x] = 0;
}

__global__ __launch_bounds__(256) void router_kernel(
    const float* __restrict__ hidden,
    const float* __restrict__ gate_w,
    const float* __restrict__ shared_gate_w,
    float* __restrict__ out_logits)
{
    const int t = blockIdx.x;
    __shared__ float sh[H_DIM];
    __shared__ float slog[NE];
    __shared__ float sred[256];

    const float* hrow = hidden + (size_t)t * H_DIM;
    for (int i = threadIdx.x; i < H_DIM; i += 256) sh[i] = hrow[i];
    __syncthreads();

    const int warp = threadIdx.x >> 5;
    const int lane = threadIdx.x & 31;

    float sum = 0.f;
    for (int k = lane; k < H_DIM; k += 32) sum += sh[k] * gate_w[k * NE + warp];
    #pragma unroll
    for (int o = 16; o; o >>= 1) sum += __shfl_down_sync(0xffffffffu, sum, o);
    if (lane == 0) slog[warp] = sum;

    float s2 = 0.f;
    for (int k = threadIdx.x; k < H_DIM; k += 256) s2 += sh[k] * shared_gate_w[k];
    sred[threadIdx.x] = s2;
    __syncthreads();
    for (int st = 128; st; st >>= 1) {
        if (threadIdx.x < st) sred[threadIdx.x] += sred[threadIdx.x + st];
        __syncthreads();
    }

    if (threadIdx.x == 0) {
        float lg[NE];
        float mx = -1e30f;
        #pragma unroll
        for (int e = 0; e < NE; ++e) { lg[e] = slog[e]; mx = fmaxf(mx, lg[e]); }
        float p[NE]; float den = 0.f;
        #pragma unroll
        for (int e = 0; e < NE; ++e) { p[e] = expf(lg[e] - mx); den += p[e]; }
        float inv = 1.f / den;
        #pragma unroll
        for (int e = 0; e < NE; ++e) {
            p[e] *= inv;
            out_logits[(size_t)t * NE + e] = lg[e];
        }
        int i0 = 0;
        #pragma unroll
        for (int e = 1; e < NE; ++e) if (p[e] > p[i0]) i0 = e;
        int i1 = -1;
        #pragma unroll
        for (int e = 0; e < NE; ++e) {
            if (e == i0) continue;
            if (i1 < 0 || p[e] > p[i1]) i1 = e;
        }
        int pos0 = atomicAdd(&g_cnt[i0], 1);
        g_tok [i0 * T_TOKENS + pos0] = t;
        g_slot[i0 * T_TOKENS + pos0] = 0;
        g_wt  [i0 * T_TOKENS + pos0] = p[i0];
        int pos1 = atomicAdd(&g_cnt[i1], 1);
        g_tok [i1 * T_TOKENS + pos1] = t;
        g_slot[i1 * T_TOKENS + pos1] = 1;
        g_wt  [i1 * T_TOKENS + pos1] = p[i1];

        g_sgate[t] = 1.f / (1.f + expf(-sred[0]));
    }
}

// ---------------------------------------------------------------------------
// fp32 -> fp16 convert (hidden + weights)
// ---------------------------------------------------------------------------
__global__ __launch_bounds__(256) void cvt_kernel(
    const float* __restrict__ src, __half* __restrict__ dst, int n4)
{
    for (int i = blockIdx.x * 256 + threadIdx.x; i < n4; i += gridDim.x * 256) {
        float4 v = ((const float4*)src)[i];
        ((__half2*)dst)[2 * i]     = __floats2half2_rn(v.x, v.y);
        ((__half2*)dst)[2 * i + 1] = __floats2half2_rn(v.z, v.w);
    }
}

// ---------------------------------------------------------------------------
// helpers
// ---------------------------------------------------------------------------
__device__ __forceinline__ uint32_t smem_u32(const void* p) {
    return (uint32_t)__cvta_generic_to_shared(p);
}
__device__ __forceinline__ void ldsm_x4(uint32_t* r, uint32_t a) {
    asm volatile("ldmatrix.sync.aligned.m8n8.x4.shared.b16 {%0,%1,%2,%3}, [%4];"
                 : "=r"(r[0]), "=r"(r[1]), "=r"(r[2]), "=r"(r[3]) : "r"(a));
}
__device__ __forceinline__ void ldsm_x4_t(uint32_t* r, uint32_t a) {
    asm volatile("ldmatrix.sync.aligned.m8n8.x4.trans.shared.b16 {%0,%1,%2,%3}, [%4];"
                 : "=r"(r[0]), "=r"(r[1]), "=r"(r[2]), "=r"(r[3]) : "r"(a));
}
__device__ __forceinline__ void mma16816(float* d, const uint32_t* a, uint32_t b0, uint32_t b1) {
    asm("mma.sync.aligned.m16n8k16.row.col.f32.f16.f16.f32 "
        "{%0,%1,%2,%3}, {%4,%5,%6,%7}, {%8,%9}, {%0,%1,%2,%3};"
        : "+f"(d[0]), "+f"(d[1]), "+f"(d[2]), "+f"(d[3])
        : "r"(a[0]), "r"(a[1]), "r"(a[2]), "r"(a[3]), "r"(b0), "r"(b1));
}
__device__ __forceinline__ uint32_t h2bits(__half2 h) {
    return *reinterpret_cast<uint32_t*>(&h);
}

#define CP16(dst, src) \
    asm volatile("cp.async.cg.shared.global [%0], [%1], 16;" :: "r"(dst), "l"(src) : "memory")
#define CP_COMMIT() asm volatile("cp.async.commit_group;" ::: "memory")
#define CP_WAIT(n)  asm volatile("cp.async.wait_group %0;" :: "n"(n) : "memory")

#define ASTRIDE 80
#define A_BYTES 10240

// ---------------------------------------------------------------------------
// FUSED gate+up GEMM (pure fp16, fp32 accum), all-cp.async 3-stage pipeline.
// blockIdx.x < 704: shared tile; else expert tile (gathered rows).
// TILE_N=128 = [gate 64 | up 64]; epilogue silu(g)*u -> fp16.
// ---------------------------------------------------------------------------
#define GU_SH_BLOCKS (SI_DIM / 64 * (T_TOKENS / 128))            // 704
#define GU_EXP_BLOCKS (I_DIM / 64 * (T_TOKENS / 128) * NE)       // 1408

__global__ void __launch_bounds__(256, 2) gateup_fused(
    const __half* __restrict__ A,
    const __half* __restrict__ wg, const __half* __restrict__ wu,
    const __half* __restrict__ swg, const __half* __restrict__ swu,
    __half* __restrict__ actO, __half* __restrict__ shO)
{
    constexpr int NW = 64, NJ = 8;
    constexpr int BSTR = 272, BSZ = 32 * BSTR;      // 8704
    constexpr int STG = A_BYTES + BSZ;              // 18944
    constexpr int K = H_DIM;

    int isExp, e, m0, n0, Ntot;
    const __half *B0, *B1;
    __half *oP;
    {
        const int bid = blockIdx.x;
        if (bid < GU_SH_BLOCKS) {
            isExp = 0; e = 0;
            m0 = (bid / (SI_DIM / 64)) * 128;
            n0 = (bid % (SI_DIM / 64)) * 64;
            Ntot = SI_DIM; B0 = swg; B1 = swu; oP = shO;
        } else {
            const int t = bid - GU_SH_BLOCKS;
            const int per_e = (I_DIM / 64) * (T_TOKENS / 128);   // 176
            isExp = 1; e = t / per_e;
            const int rem = t % per_e;
            m0 = (rem / (I_DIM / 64)) * 128;
            n0 = (rem % (I_DIM / 64)) * 64;
            Ntot = I_DIM; B0 = wg; B1 = wu; oP = actO;
        }
    }
    const int cnt = isExp ? g_cnt[e] : T_TOKENS;
    if (m0 >= cnt) return;

    extern __shared__ char db[];
    __shared__ int s_tok[128];

    const int tid  = threadIdx.x;
    const int lane = tid & 31;
    const int warp = tid >> 5;
    const int wm = warp & 3;
    const int wn = warp >> 2;

    if (isExp && tid < 128) {
        int gm = m0 + tid;
        s_tok[tid] = (gm < cnt) ? g_tok[e * T_TOKENS + gm] : 0;
    }
    __syncthreads();

    // ---- A loader: thread -> row tid>>1, 16 k halves at (tid&1)*16 ----
    const int arow_l = tid >> 1;
    size_t arow = isExp ? (size_t)s_tok[arow_l] : (size_t)(m0 + arow_l);
    const __half* aP = A + arow * K + (tid & 1) * 16;
    const uint32_t aDst = smem_u32(db) + (uint32_t)(arow_l * ASTRIDE + (tid & 1) * 32);

    // ---- B loader (fp16 cp.async): k-row tid>>3, 16 halves at (tid&7)*16 ----
    const int bkr = tid >> 3;
    const int seg = (tid & 7) * 16;
    const size_t eoff = isExp ? (size_t)e * K * Ntot : 0;
    const __half* BP = (seg < NW ? B0 + eoff + n0 + seg : B1 + eoff + n0 + seg - NW)
                       + (size_t)bkr * Ntot;
    const uint32_t bDst = smem_u32(db) + (uint32_t)(A_BYTES + bkr * BSTR + seg * 2);

    auto issue = [&](int k0, int s) {
        const uint32_t so = (uint32_t)(s * STG);
        CP16(aDst + so,      aP + k0);
        CP16(aDst + so + 16, aP + k0 + 8);
        const __half* bp = BP + (size_t)k0 * Ntot;
        CP16(bDst + so,      bp);
        CP16(bDst + so + 16, bp + 8);
    };

    float acc[2][NJ][4];
    #pragma unroll
    for (int i = 0; i < 2; ++i)
        #pragma unroll
        for (int j = 0; j < NJ; ++j)
            #pragma unroll
            for (int v = 0; v < 4; ++v) acc[i][j][v] = 0.f;

    const int grp = lane >> 3;
    const int gl  = lane & 7;
    const int a_row_off = (grp & 1) * 8 + gl;
    const int a_col_off = (grp >> 1) * 8;
    const int b_row_off = (grp & 1) * 8 + gl;
    const int b_col_off = (grp >> 1) * 8;

    const int C = K / 32;
    issue(0, 0); CP_COMMIT();
    issue(32, 1); CP_COMMIT();
    issue(64, 2); CP_COMMIT();

    for (int c = 0; c < C; ++c) {
        CP_WAIT(2);
        __syncthreads();

        const uint32_t base = smem_u32(db) + (uint32_t)((c % 3) * STG);
        #pragma unroll
        for (int ks = 0; ks < 32; ks += 16) {
            uint32_t ah[2][4];
            #pragma unroll
            for (int mi = 0; mi < 2; ++mi) {
                const uint32_t ra = base + (uint32_t)((wm * 32 + mi * 16 + a_row_off) * ASTRIDE + (ks + a_col_off) * 2);
                ldsm_x4(ah[mi], ra);
            }
            #pragma unroll
            for (int g = 0; g < NW / 16; ++g) {
                uint32_t bh[4];
                const uint32_t rb = base + (uint32_t)(A_BYTES + (ks + b_row_off) * BSTR + (wn * NW + g * 16 + b_col_off) * 2);
                ldsm_x4_t(bh, rb);
                #pragma unroll
                for (int mi = 0; mi < 2; ++mi)
                    #pragma unroll
                    for (int half = 0; half < 2; ++half)
                        mma16816(acc[mi][g * 2 + half], ah[mi], bh[half * 2], bh[half * 2 + 1]);
            }
        }
        __syncthreads();
        if (c + 3 < C) issue((c + 3) * 32, c % 3);
        CP_COMMIT();
    }

    // ---- epilogue: silu(g)*u -> fp16 ----
    constexpr int EXS = NW + 8;
    float* exch = (float*)db;
    if (wn == 1) {
        #pragma unroll
        for (int mi = 0; mi < 2; ++mi)
            #pragma unroll
            for (int nj = 0; nj < NJ; ++nj) {
                const int cl = nj * 8 + (lane & 3) * 2;
                #pragma unroll
                for (int h = 0; h < 2; ++h) {
                    const int rl = wm * 32 + mi * 16 + (lane >> 2) + h * 8;
                    exch[rl * EXS + cl]     = acc[mi][nj][h * 2];
                    exch[rl * EXS + cl + 1] = acc[mi][nj][h * 2 + 1];
                }
            }
    }
    __syncthreads();
    if (wn == 0) {
        #pragma unroll
        for (int mi = 0; mi < 2; ++mi)
            #pragma unroll
            for (int h = 0; h < 2; ++h) {
                const int rl = wm * 32 + mi * 16 + (lane >> 2) + h * 8;
                const int r = m0 + rl;
                if (isExp && r >= cnt) continue;
                const size_t row = (isExp ? (size_t)e * T_TOKENS : 0) + r;
                #pragma unroll
                for (int nj = 0; nj < NJ; ++nj) {
                    const int cl = nj * 8 + (lane & 3) * 2;
                    const float g0 = acc[mi][nj][h * 2];
                    const float g1 = acc[mi][nj][h * 2 + 1];
                    const float u0 = exch[rl * EXS + cl];
                    const float u1 = exch[rl * EXS + cl + 1];
                    const float a0 = (g0 / (1.f + expf(-g0))) * u0;
                    const float a1 = (g1 / (1.f + expf(-g1))) * u1;
                    *(uint32_t*)(oP + row * Ntot + n0 + cl) = h2bits(__floats2half2_rn(a0, a1));
                }
            }
    }
}

// ---------------------------------------------------------------------------
// Down GEMM (pure fp16, all-cp.async 3-stage). EPI=1: expert scatter x weight.
// EPI=2: shared combine (sigmoid gate + contrib -> outF).
// ---------------------------------------------------------------------------
template<int AEXP, int EPI, int TILE_N>
__global__ void __launch_bounds__(256, 2) down_gemm(
    const __half* __restrict__ A,
    const __half* __restrict__ B0,
    float* __restrict__ outF, int K, int Ntot)
{
    constexpr int NW   = TILE_N / 2;
    constexpr int NJ   = NW / 8;
    constexpr int CPT  = TILE_N / 8;            // halves per loader thread
    constexpr int BSTR = TILE_N * 2 + 16;
    constexpr int BSZ  = 32 * BSTR;
    constexpr int STG  = A_BYTES + BSZ;

    const int e  = blockIdx.z;
    const int m0 = blockIdx.y * 128;
    const int n0 = blockIdx.x * TILE_N;
    const int cnt = AEXP ? g_cnt[e] : T_TOKENS;
    if (m0 >= cnt) return;

    extern __shared__ char db[];

    const int tid  = threadIdx.x;
    const int lane = tid & 31;
    const int warp = tid >> 5;
    const int wm = warp & 3;
    const int wn = warp >> 2;

    const int arow_l = tid >> 1;
    const size_t arow = (AEXP ? (size_t)e * T_TOKENS : 0) + m0 + arow_l;
    const __half* aP = A + arow * K + (tid & 1) * 16;
    const uint32_t aDst = smem_u32(db) + (uint32_t)(arow_l * ASTRIDE + (tid & 1) * 32);

    const int bkr = tid >> 3;
    const int seg = (tid & 7) * CPT;
    const size_t eoff = AEXP ? (size_t)e * K * Ntot : 0;
    const __half* BP = B0 + eoff + n0 + seg + (size_t)bkr * Ntot;
    const uint32_t bDst = smem_u32(db) + (uint32_t)(A_BYTES + bkr * BSTR + seg * 2);

    auto issue = [&](int k0, int s) {
        const uint32_t so = (uint32_t)(s * STG);
        CP16(aDst + so,      aP + k0);
        CP16(aDst + so + 16, aP + k0 + 8);
        const __half* bp = BP + (size_t)k0 * Ntot;
        CP16(bDst + so, bp);
        if (CPT == 16) CP16(bDst + so + 16, bp + 8);
    };

    float acc[2][NJ][4];
    #pragma unroll
    for (int i = 0; i < 2; ++i)
        #pragma unroll
        for (int j = 0; j < NJ; ++j)
            #pragma unroll
            for (int v = 0; v < 4; ++v) acc[i][j][v] = 0.f;

    const int grp = lane >> 3;
    const int gl  = lane & 7;
    const int a_row_off = (grp & 1) * 8 + gl;
    const int a_col_off = (grp >> 1) * 8;
    const int b_row_off = (grp & 1) * 8 + gl;
    const int b_col_off = (grp >> 1) * 8;

    const int C = K / 32;
    issue(0, 0); CP_COMMIT();
    issue(32, 1); CP_COMMIT();
    issue(64, 2); CP_COMMIT();

    for (int c = 0; c < C; ++c) {
        CP_WAIT(2);
        __syncthreads();

        const uint32_t base = smem_u32(db) + (uint32_t)((c % 3) * STG);
        #pragma unroll
        for (int ks = 0; ks < 32; ks += 16) {
            uint32_t ah[2][4];
            #pragma unroll
            for (int mi = 0; mi < 2; ++mi) {
                const uint32_t ra = base + (uint32_t)((wm * 32 + mi * 16 + a_row_off) * ASTRIDE + (ks + a_col_off) * 2);
                ldsm_x4(ah[mi], ra);
            }
            #pragma unroll
            for (int g = 0; g < NW / 16; ++g) {
                uint32_t bh[4];
                const uint32_t rb = base + (uint32_t)(A_BYTES + (ks + b_row_off) * BSTR + (wn * NW + g * 16 + b_col_off) * 2);
                ldsm_x4_t(bh, rb);
                #pragma unroll
                for (int mi = 0; mi < 2; ++mi)
                    #pragma unroll
                    for (int half = 0; half < 2; ++half)
                        mma16816(acc[mi][g * 2 + half], ah[mi], bh[half * 2], bh[half * 2 + 1]);
            }
        }
        __syncthreads();
        if (c + 3 < C) issue((c + 3) * 32, c % 3);
        CP_COMMIT();
    }

    #pragma unroll
    for (int mi = 0; mi < 2; ++mi)
        #pragma unroll
        for (int h = 0; h < 2; ++h) {
            const int rl = wm * 32 + mi * 16 + (lane >> 2) + h * 8;
            const int r = m0 + rl;
            if (EPI == 1) {
                if (r >= cnt) continue;
                const int idx = e * T_TOKENS + r;
                const float w = g_wt[idx];
                float* orow = g_contrib + ((size_t)g_tok[idx] * 2 + g_slot[idx]) * H_DIM;
                #pragma unroll
                for (int nj = 0; nj < NJ; ++nj) {
                    const int c = n0 + wn * NW + nj * 8 + (lane & 3) * 2;
                    float2 o = {acc[mi][nj][h * 2] * w, acc[mi][nj][h * 2 + 1] * w};
                    *(float2*)(orow + c) = o;
                }
            } else {
                const float sg = g_sgate[r];
                #pragma unroll
                for (int nj = 0; nj < NJ; ++nj) {
                    const int c = n0 + wn * NW + nj * 8 + (lane & 3) * 2;
                    const float2 c0 = *(const float2*)(g_contrib + ((size_t)r * 2 + 0) * H_DIM + c);
                    const float2 c1 = *(const float2*)(g_contrib + ((size_t)r * 2 + 1) * H_DIM + c);
                    float2 o = {sg * acc[mi][nj][h * 2] + c0.x + c1.x,
                                sg * acc[mi][nj][h * 2 + 1] + c0.y + c1.y};
                    *(float2*)(outF + (size_t)r * H_DIM + c) = o;
                }
            }
        }
}

// ---------------------------------------------------------------------------
extern "C" void kernel_launch(void* const* d_in, const int* in_sizes, int n_in,
                              void* d_out, int out_size)
{
    const float* hidden        = (const float*)d_in[0];
    const float* gate_w        = (const float*)d_in[1];
    const float* w_gate        = (const float*)d_in[2];
    const float* w_up          = (const float*)d_in[3];
    const float* w_down        = (const float*)d_in[4];
    const float* sw_gate       = (const float*)d_in[5];
    const float* sw_up         = (const float*)d_in[6];
    const float* sw_down       = (const float*)d_in[7];
    const float* shared_gate_w = (const float*)d_in[8];

    float* out        = (float*)d_out;
    float* out_logits = out + (size_t)T_TOKENS * H_DIM;

    __half *hid, *act, *shact;
    __half *wg16, *wu16, *wd16, *swg16, *swu16, *swd16;
    cudaGetSymbolAddress((void**)&hid, g_hid);
    cudaGetSymbolAddress((void**)&act, g_act);
    cudaGetSymbolAddress((void**)&shact, g_shact);
    cudaGetSymbolAddress((void**)&wg16, g_wg16);
    cudaGetSymbolAddress((void**)&wu16, g_wu16);
    cudaGetSymbolAddress((void**)&wd16, g_wd16);
    cudaGetSymbolAddress((void**)&swg16, g_swg16);
    cudaGetSymbolAddress((void**)&swu16, g_swu16);
    cudaGetSymbolAddress((void**)&swd16, g_swd16);

    const int SM128 = 3 * (A_BYTES + 32 * (128 * 2 + 16));  // 56832
    const int SM64  = 3 * (A_BYTES + 32 * (64 * 2 + 16));   // 44544

    cudaFuncSetAttribute(gateup_fused,        cudaFuncAttributeMaxDynamicSharedMemorySize, SM128);
    cudaFuncSetAttribute(down_gemm<1,1,128>,  cudaFuncAttributeMaxDynamicSharedMemorySize, SM128);
    cudaFuncSetAttribute(down_gemm<0,2,64>,   cudaFuncAttributeMaxDynamicSharedMemorySize, SM64);

    zero_cnt_kernel<<<1, 32>>>();
    router_kernel<<<T_TOKENS, 256>>>(hidden, gate_w, shared_gate_w, out_logits);

    // conversions to fp16 (memory-bound)
    auto cvt = [&](const float* s, __half* d, size_t n) {
        int n4 = (int)(n / 4);
        int grid = (n4 + 255) / 256; if (grid > 4096) grid = 4096;
        cvt_kernel<<<grid, 256>>>(s, d, n4);
    };
    cvt(hidden,  hid,   (size_t)T_TOKENS * H_DIM);
    cvt(w_gate,  wg16,  (size_t)NE * H_DIM * I_DIM);
    cvt(w_up,    wu16,  (size_t)NE * H_DIM * I_DIM);
    cvt(w_down,  wd16,  (size_t)NE * I_DIM * H_DIM);
    cvt(sw_gate, swg16, (size_t)H_DIM * SI_DIM);
    cvt(sw_up,   swu16, (size_t)H_DIM * SI_DIM);
    cvt(sw_down, swd16, (size_t)SI_DIM * H_DIM);

    // fused expert+shared gate/up (wave-packed single launch)
    gateup_fused<<<GU_SH_BLOCKS + GU_EXP_BLOCKS, 256, SM128>>>(
        hid, wg16, wu16, swg16, swu16, act, shact);

    // expert down -> contrib scatter
    down_gemm<1,1,128><<<dim3(H_DIM / 128, T_TOKENS / 128, NE), 256, SM128>>>(
        act, wd16, nullptr, I_DIM, H_DIM);

    // shared down + combine -> out
    down_gemm<0,2,64><<<dim3(H_DIM / 64, T_TOKENS / 128, 1), 256, SM64>>>(
        shact, swd16, out, SI_DIM, H_DIM);
}